// round 2
// baseline (speedup 1.0000x reference)
#include <cuda_runtime.h>
#include <math.h>

#define NN    50000
#define EE    400000
#define ETOT  (NN + EE)
#define C1    256      // HEADS*HID and OUT
#define KIN   20
#define NEG_SLOPE 0.2f
#define EPSS  1e-16f

// ---------------- scratch (static device globals; no allocations) ----------
__device__ float g_xl1[NN * C1];
__device__ float g_xr1[NN * C1];
__device__ float g_out1[NN * C1];   // layer-1 aggregate (pre-ELU)
__device__ float g_h[NN * C1];      // ELU(out1)
__device__ float g_xl2[NN * C1];
__device__ float g_xr2[NN * C1];
__device__ float g_lw1[ETOT * 4];   // per-edge logits, then exp weights
__device__ float g_lw2[ETOT];
__device__ float g_max1[NN * 4];
__device__ float g_sum1[NN * 4];
__device__ float g_max2[NN];
__device__ float g_sum2[NN];

// ---------------- helpers ----------------
__device__ __forceinline__ float atomicMaxFloat(float* addr, float value) {
    if (value >= 0.0f)
        return __int_as_float(atomicMax((int*)addr, __float_as_int(value)));
    else
        return __uint_as_float(atomicMin((unsigned int*)addr, __float_as_uint(value)));
}

__device__ __forceinline__ float lrelu(float v) {
    return v > 0.0f ? v : NEG_SLOPE * v;
}

// ---------------- init ----------------
__global__ void init_kernel(const float* __restrict__ bias1,
                            const float* __restrict__ bias2,
                            float* __restrict__ out) {
    int idx = blockIdx.x * blockDim.x + threadIdx.x;
    if (idx < NN * C1) {
        g_out1[idx] = bias1[idx & 255];
        out[idx]    = bias2[idx & 255];
    }
    if (idx < NN * 4) {
        g_max1[idx] = -INFINITY;
        g_sum1[idx] = 0.0f;
    }
    if (idx < NN) {
        g_max2[idx] = -INFINITY;
        g_sum2[idx] = 0.0f;
    }
}

// ---------------- layer-1 GEMM: x[N,20] @ W[20,256] (+b), two outputs ------
__global__ void gemm1_kernel(const float* __restrict__ x,
                             const float* __restrict__ Wl, const float* __restrict__ bl,
                             const float* __restrict__ Wr, const float* __restrict__ br) {
    __shared__ float swl[KIN * 256];
    __shared__ float swr[KIN * 256];
    __shared__ float sx[16][KIN];
    int tid = threadIdx.x;
    for (int i = tid; i < KIN * 256; i += 256) { swl[i] = Wl[i]; swr[i] = Wr[i]; }
    int nb = blockIdx.x * 16;
    for (int i = tid; i < 16 * KIN; i += 256) {
        int node = nb + i / KIN;
        sx[i / KIN][i % KIN] = (node < NN) ? x[node * KIN + (i % KIN)] : 0.0f;
    }
    __syncthreads();
    float bL = bl[tid], bR = br[tid];
    for (int i = 0; i < 16; i++) {
        int node = nb + i;
        if (node >= NN) break;
        float al = bL, ar = bR;
        #pragma unroll
        for (int k = 0; k < KIN; k++) {
            float xv = sx[i][k];
            al = fmaf(xv, swl[k * 256 + tid], al);
            ar = fmaf(xv, swr[k * 256 + tid], ar);
        }
        g_xl1[node * 256 + tid] = al;
        g_xr1[node * 256 + tid] = ar;
    }
}

// ---------------- layer-2 GEMM: g_h[N,256] @ W[256,256] + bias -------------
// SEL=0 -> writes g_xl2, SEL=1 -> writes g_xr2. A is always g_h.
// (NOTE: __device__ globals must NOT be passed as host-side kernel args —
//  on GB300 ATS maps the host shadow symbol and silently reads zeros.)
template<int SEL>
__global__ void gemm256_kernel(const float* __restrict__ W,
                               const float* __restrict__ bias) {
    const float* __restrict__ A = g_h;
    float* __restrict__ C = (SEL == 0) ? g_xl2 : g_xr2;

    __shared__ float As[16][64];
    __shared__ float Bs[16][64];
    int tid = threadIdx.x;
    int tx = tid & 15;          // col group
    int ty = tid >> 4;          // row group
    int row0 = blockIdx.x * 64;
    int col0 = blockIdx.y * 64;

    float acc[4][4];
    #pragma unroll
    for (int i = 0; i < 4; i++)
        #pragma unroll
        for (int j = 0; j < 4; j++) acc[i][j] = 0.0f;

    for (int kt = 0; kt < 256; kt += 16) {
        #pragma unroll
        for (int j = 0; j < 4; j++) {
            int i = tid + j * 256;
            int m = i >> 4, k = i & 15;
            int row = row0 + m;
            As[k][m] = (row < NN) ? A[row * 256 + kt + k] : 0.0f;
        }
        #pragma unroll
        for (int j = 0; j < 4; j++) {
            int i = tid + j * 256;
            int k = i >> 6, col = i & 63;
            Bs[k][col] = W[(kt + k) * 256 + col0 + col];
        }
        __syncthreads();
        #pragma unroll
        for (int k = 0; k < 16; k++) {
            float4 a = *(const float4*)&As[k][ty * 4];
            float4 b = *(const float4*)&Bs[k][tx * 4];
            acc[0][0] = fmaf(a.x, b.x, acc[0][0]); acc[0][1] = fmaf(a.x, b.y, acc[0][1]);
            acc[0][2] = fmaf(a.x, b.z, acc[0][2]); acc[0][3] = fmaf(a.x, b.w, acc[0][3]);
            acc[1][0] = fmaf(a.y, b.x, acc[1][0]); acc[1][1] = fmaf(a.y, b.y, acc[1][1]);
            acc[1][2] = fmaf(a.y, b.z, acc[1][2]); acc[1][3] = fmaf(a.y, b.w, acc[1][3]);
            acc[2][0] = fmaf(a.z, b.x, acc[2][0]); acc[2][1] = fmaf(a.z, b.y, acc[2][1]);
            acc[2][2] = fmaf(a.z, b.z, acc[2][2]); acc[2][3] = fmaf(a.z, b.w, acc[2][3]);
            acc[3][0] = fmaf(a.w, b.x, acc[3][0]); acc[3][1] = fmaf(a.w, b.y, acc[3][1]);
            acc[3][2] = fmaf(a.w, b.z, acc[3][2]); acc[3][3] = fmaf(a.w, b.w, acc[3][3]);
        }
        __syncthreads();
    }
    #pragma unroll
    for (int i = 0; i < 4; i++) {
        int row = row0 + ty * 4 + i;
        if (row >= NN) continue;
        int col = col0 + tx * 4;
        float4 v;
        v.x = acc[i][0] + bias[col + 0];
        v.y = acc[i][1] + bias[col + 1];
        v.z = acc[i][2] + bias[col + 2];
        v.w = acc[i][3] + bias[col + 3];
        *(float4*)&C[row * 256 + col] = v;
    }
}

// ---------------- layer-1 edge logits + segment max (warp per edge) --------
__global__ void edge_logits_max1(const int* __restrict__ ei,
                                 const float* __restrict__ att) {
    int warp = (blockIdx.x * blockDim.x + threadIdx.x) >> 5;
    int lane = threadIdx.x & 31;
    if (warp >= ETOT) return;
    int src, dst;
    if (warp < EE) { src = ei[warp]; dst = ei[EE + warp]; }
    else           { src = dst = warp - EE; }
    int c = lane * 8;
    const float4* pl = (const float4*)(g_xl1 + src * C1 + c);
    const float4* pr = (const float4*)(g_xr1 + dst * C1 + c);
    const float4* pa = (const float4*)(att + c);
    float p = 0.0f;
    #pragma unroll
    for (int j = 0; j < 2; j++) {
        float4 a = pl[j], b = pr[j], w = pa[j];
        p = fmaf(w.x, lrelu(a.x + b.x), p);
        p = fmaf(w.y, lrelu(a.y + b.y), p);
        p = fmaf(w.z, lrelu(a.z + b.z), p);
        p = fmaf(w.w, lrelu(a.w + b.w), p);
    }
    p += __shfl_down_sync(0xffffffffu, p, 4);
    p += __shfl_down_sync(0xffffffffu, p, 2);
    p += __shfl_down_sync(0xffffffffu, p, 1);
    if ((lane & 7) == 0) {
        int h = lane >> 3;
        g_lw1[warp * 4 + h] = p;
        atomicMaxFloat(&g_max1[dst * 4 + h], p);
    }
}

// ---------------- layer-1 exp + segment sum (thread per edge) --------------
__global__ void edge_exp_sum1(const int* __restrict__ ei) {
    int e = blockIdx.x * blockDim.x + threadIdx.x;
    if (e >= ETOT) return;
    int dst = (e < EE) ? ei[EE + e] : e - EE;
    float4 l = *(const float4*)(g_lw1 + e * 4);
    float4 m = *(const float4*)(g_max1 + dst * 4);
    float w0 = __expf(l.x - m.x);
    float w1 = __expf(l.y - m.y);
    float w2 = __expf(l.z - m.z);
    float w3 = __expf(l.w - m.w);
    *(float4*)(g_lw1 + e * 4) = make_float4(w0, w1, w2, w3);
    atomicAdd(&g_sum1[dst * 4 + 0], w0);
    atomicAdd(&g_sum1[dst * 4 + 1], w1);
    atomicAdd(&g_sum1[dst * 4 + 2], w2);
    atomicAdd(&g_sum1[dst * 4 + 3], w3);
}

// ---------------- layer-1 aggregate (warp per edge, atomics into out1) -----
__global__ void edge_aggregate1(const int* __restrict__ ei) {
    int warp = (blockIdx.x * blockDim.x + threadIdx.x) >> 5;
    int lane = threadIdx.x & 31;
    if (warp >= ETOT) return;
    int src, dst;
    if (warp < EE) { src = ei[warp]; dst = ei[EE + warp]; }
    else           { src = dst = warp - EE; }
    int h = lane >> 3;
    int c = lane * 8;
    float w = g_lw1[warp * 4 + h];
    float s = g_sum1[dst * 4 + h];
    float alpha = w / (s + EPSS);
    const float4* pl = (const float4*)(g_xl1 + src * C1 + c);
    float* o = g_out1 + dst * C1 + c;
    float4 a0 = pl[0], a1 = pl[1];
    atomicAdd(o + 0, alpha * a0.x);
    atomicAdd(o + 1, alpha * a0.y);
    atomicAdd(o + 2, alpha * a0.z);
    atomicAdd(o + 3, alpha * a0.w);
    atomicAdd(o + 4, alpha * a1.x);
    atomicAdd(o + 5, alpha * a1.y);
    atomicAdd(o + 6, alpha * a1.z);
    atomicAdd(o + 7, alpha * a1.w);
}

// ---------------- ELU ----------------
__global__ void elu_kernel() {
    int idx = blockIdx.x * blockDim.x + threadIdx.x;
    if (idx >= NN * C1) return;
    float v = g_out1[idx];
    g_h[idx] = v > 0.0f ? v : expm1f(v);
}

// ---------------- layer-2 edge logits + max (warp per edge, 1 head) --------
__global__ void edge_logits_max2(const int* __restrict__ ei,
                                 const float* __restrict__ att) {
    int warp = (blockIdx.x * blockDim.x + threadIdx.x) >> 5;
    int lane = threadIdx.x & 31;
    if (warp >= ETOT) return;
    int src, dst;
    if (warp < EE) { src = ei[warp]; dst = ei[EE + warp]; }
    else           { src = dst = warp - EE; }
    int c = lane * 8;
    const float4* pl = (const float4*)(g_xl2 + src * C1 + c);
    const float4* pr = (const float4*)(g_xr2 + dst * C1 + c);
    const float4* pa = (const float4*)(att + c);
    float p = 0.0f;
    #pragma unroll
    for (int j = 0; j < 2; j++) {
        float4 a = pl[j], b = pr[j], w = pa[j];
        p = fmaf(w.x, lrelu(a.x + b.x), p);
        p = fmaf(w.y, lrelu(a.y + b.y), p);
        p = fmaf(w.z, lrelu(a.z + b.z), p);
        p = fmaf(w.w, lrelu(a.w + b.w), p);
    }
    #pragma unroll
    for (int off = 16; off > 0; off >>= 1)
        p += __shfl_down_sync(0xffffffffu, p, off);
    if (lane == 0) {
        g_lw2[warp] = p;
        atomicMaxFloat(&g_max2[dst], p);
    }
}

// ---------------- layer-2 exp + sum ----------------
__global__ void edge_exp_sum2(const int* __restrict__ ei) {
    int e = blockIdx.x * blockDim.x + threadIdx.x;
    if (e >= ETOT) return;
    int dst = (e < EE) ? ei[EE + e] : e - EE;
    float w = __expf(g_lw2[e] - g_max2[dst]);
    g_lw2[e] = w;
    atomicAdd(&g_sum2[dst], w);
}

// ---------------- layer-2 aggregate into final output ----------------
__global__ void edge_aggregate2(const int* __restrict__ ei,
                                float* __restrict__ out) {
    int warp = (blockIdx.x * blockDim.x + threadIdx.x) >> 5;
    int lane = threadIdx.x & 31;
    if (warp >= ETOT) return;
    int src, dst;
    if (warp < EE) { src = ei[warp]; dst = ei[EE + warp]; }
    else           { src = dst = warp - EE; }
    float w = g_lw2[warp];
    float s = g_sum2[dst];
    float alpha = w / (s + EPSS);
    int c = lane * 8;
    const float4* pl = (const float4*)(g_xl2 + src * C1 + c);
    float* o = out + dst * C1 + c;
    float4 a0 = pl[0], a1 = pl[1];
    atomicAdd(o + 0, alpha * a0.x);
    atomicAdd(o + 1, alpha * a0.y);
    atomicAdd(o + 2, alpha * a0.z);
    atomicAdd(o + 3, alpha * a0.w);
    atomicAdd(o + 4, alpha * a1.x);
    atomicAdd(o + 5, alpha * a1.y);
    atomicAdd(o + 6, alpha * a1.z);
    atomicAdd(o + 7, alpha * a1.w);
}

// ---------------- launcher ----------------
extern "C" void kernel_launch(void* const* d_in, const int* in_sizes, int n_in,
                              void* d_out, int out_size) {
    const float* x     = (const float*)d_in[0];
    const int*   ei    = (const int*)  d_in[1];
    const float* W_l1  = (const float*)d_in[2];
    const float* b_l1  = (const float*)d_in[3];
    const float* W_r1  = (const float*)d_in[4];
    const float* b_r1  = (const float*)d_in[5];
    const float* att1  = (const float*)d_in[6];
    const float* bias1 = (const float*)d_in[7];
    const float* W_l2  = (const float*)d_in[8];
    const float* b_l2  = (const float*)d_in[9];
    const float* W_r2  = (const float*)d_in[10];
    const float* b_r2  = (const float*)d_in[11];
    const float* att2  = (const float*)d_in[12];
    const float* bias2 = (const float*)d_in[13];
    float* out = (float*)d_out;

    const int T = 256;
    int blk_elem  = (NN * C1 + T - 1) / T;          // 50000
    int blk_edgeW = (ETOT * 32 + T - 1) / T;        // warp-per-edge
    int blk_edgeT = (ETOT + T - 1) / T;             // thread-per-edge
    int blk_g1    = (NN + 15) / 16;                 // 3125

    init_kernel<<<blk_elem, T>>>(bias1, bias2, out);
    gemm1_kernel<<<blk_g1, T>>>(x, W_l1, b_l1, W_r1, b_r1);
    edge_logits_max1<<<blk_edgeW, T>>>(ei, att1);
    edge_exp_sum1<<<blk_edgeT, T>>>(ei);
    edge_aggregate1<<<blk_edgeW, T>>>(ei);
    elu_kernel<<<blk_elem, T>>>();

    dim3 g2((NN + 63) / 64, 4);
    gemm256_kernel<0><<<g2, T>>>(W_l2, b_l2);
    gemm256_kernel<1><<<g2, T>>>(W_r2, b_r2);

    edge_logits_max2<<<blk_edgeW, T>>>(ei, att2);
    edge_exp_sum2<<<blk_edgeT, T>>>(ei);
    edge_aggregate2<<<blk_edgeW, T>>>(ei, out);
}

// round 3
// speedup vs baseline: 2.3782x; 2.3782x over previous
#include <cuda_runtime.h>
#include <math.h>

#define NN    50000
#define EE    400000
#define ETOT  (NN + EE)
#define C1    256
#define KIN   20
#define NEG_SLOPE 0.2f
#define EPSS  1e-16f

// ---------------- scratch (static device globals; no allocations) ----------
__device__ float g_xl1[NN * C1];
__device__ float g_xr1[NN * C1];
__device__ float g_h[NN * C1];      // ELU(layer-1 output)
__device__ float g_xl2[NN * C1];
__device__ float g_xr2[NN * C1];
__device__ float g_lw1[ETOT * 4];   // logits -> normalized alpha (layer 1)
__device__ float g_lw2[ETOT];       // logits -> normalized alpha (layer 2)
__device__ int   g_deg[NN];         // degree counts, then scatter cursor
__device__ int   g_off[NN + 1];     // CSR offsets
__device__ int   g_csr_src[ETOT];
__device__ int   g_csr_dst[ETOT];

__device__ __forceinline__ float lrelu(float v) {
    return v > 0.0f ? v : NEG_SLOPE * v;
}

// ================= CSR construction =================
__global__ void zero_deg() {
    int i = blockIdx.x * blockDim.x + threadIdx.x;
    if (i < NN) g_deg[i] = 0;
}

__global__ void csr_count(const int* __restrict__ ei) {
    int e = blockIdx.x * blockDim.x + threadIdx.x;
    if (e >= ETOT) return;
    int dst = (e < EE) ? ei[EE + e] : e - EE;
    atomicAdd(&g_deg[dst], 1);
}

// single-block exclusive scan over g_deg -> g_off; also zeroes g_deg (cursor)
__global__ void csr_scan() {
    int tid = threadIdx.x;
    int lane = tid & 31, wid = tid >> 5;
    __shared__ int wsum[32];
    __shared__ int carry_s;
    if (tid == 0) carry_s = 0;
    __syncthreads();
    for (int base = 0; base < NN; base += 1024) {
        __syncthreads();
        int i = base + tid;
        int v = (i < NN) ? g_deg[i] : 0;
        if (i < NN) g_deg[i] = 0;
        int x = v;
        #pragma unroll
        for (int o = 1; o < 32; o <<= 1) {
            int y = __shfl_up_sync(0xffffffffu, x, o);
            if (lane >= o) x += y;
        }
        if (lane == 31) wsum[wid] = x;
        __syncthreads();
        if (wid == 0) {
            int w = wsum[lane];
            #pragma unroll
            for (int o = 1; o < 32; o <<= 1) {
                int y = __shfl_up_sync(0xffffffffu, w, o);
                if (lane >= o) w += y;
            }
            wsum[lane] = w;
        }
        __syncthreads();
        int blockincl = x + (wid > 0 ? wsum[wid - 1] : 0);
        int excl = carry_s + blockincl - v;
        if (i < NN) g_off[i] = excl;
        __syncthreads();
        if (tid == 1023) carry_s += blockincl;
    }
    __syncthreads();
    if (tid == 0) g_off[NN] = carry_s;
}

__global__ void csr_scatter(const int* __restrict__ ei) {
    int e = blockIdx.x * blockDim.x + threadIdx.x;
    if (e >= ETOT) return;
    int src, dst;
    if (e < EE) { src = ei[e]; dst = ei[EE + e]; }
    else        { src = dst = e - EE; }
    int pos = g_off[dst] + atomicAdd(&g_deg[dst], 1);
    g_csr_src[pos] = src;
    g_csr_dst[pos] = dst;
}

// ================= layer-1 GEMM: x[N,20]@W[20,256]+b (two outputs) =========
__global__ void gemm1_kernel(const float* __restrict__ x,
                             const float* __restrict__ Wl, const float* __restrict__ bl,
                             const float* __restrict__ Wr, const float* __restrict__ br) {
    __shared__ float swl[KIN * 256];
    __shared__ float swr[KIN * 256];
    __shared__ float sx[16][KIN];
    int tid = threadIdx.x;
    for (int i = tid; i < KIN * 256; i += 256) { swl[i] = Wl[i]; swr[i] = Wr[i]; }
    int nb = blockIdx.x * 16;
    for (int i = tid; i < 16 * KIN; i += 256) {
        int node = nb + i / KIN;
        sx[i / KIN][i % KIN] = (node < NN) ? x[node * KIN + (i % KIN)] : 0.0f;
    }
    __syncthreads();
    float bL = bl[tid], bR = br[tid];
    for (int i = 0; i < 16; i++) {
        int node = nb + i;
        if (node >= NN) break;
        float al = bL, ar = bR;
        #pragma unroll
        for (int k = 0; k < KIN; k++) {
            float xv = sx[i][k];
            al = fmaf(xv, swl[k * 256 + tid], al);
            ar = fmaf(xv, swr[k * 256 + tid], ar);
        }
        g_xl1[node * 256 + tid] = al;
        g_xr1[node * 256 + tid] = ar;
    }
}

// ================= dual layer-2 GEMM: g_h @ {W_l2, W_r2} -> g_xl2, g_xr2 ====
__global__ void gemm_dual(const float* __restrict__ Wl, const float* __restrict__ bl,
                          const float* __restrict__ Wr, const float* __restrict__ br) {
    const float* __restrict__ A = g_h;
    __shared__ float As[16][64];
    __shared__ float Bl[16][64];
    __shared__ float Br[16][64];
    int tid = threadIdx.x;
    int tx = tid & 15;
    int ty = tid >> 4;
    int row0 = blockIdx.x * 64;
    int col0 = blockIdx.y * 64;

    float accL[4][4], accR[4][4];
    #pragma unroll
    for (int i = 0; i < 4; i++)
        #pragma unroll
        for (int j = 0; j < 4; j++) { accL[i][j] = 0.0f; accR[i][j] = 0.0f; }

    for (int kt = 0; kt < 256; kt += 16) {
        #pragma unroll
        for (int j = 0; j < 4; j++) {
            int i = tid + j * 256;
            int m = i >> 4, k = i & 15;
            int row = row0 + m;
            As[k][m] = (row < NN) ? A[row * 256 + kt + k] : 0.0f;
        }
        #pragma unroll
        for (int j = 0; j < 4; j++) {
            int i = tid + j * 256;
            int k = i >> 6, col = i & 63;
            Bl[k][col] = Wl[(kt + k) * 256 + col0 + col];
            Br[k][col] = Wr[(kt + k) * 256 + col0 + col];
        }
        __syncthreads();
        #pragma unroll
        for (int k = 0; k < 16; k++) {
            float4 a  = *(const float4*)&As[k][ty * 4];
            float4 b  = *(const float4*)&Bl[k][tx * 4];
            float4 b2 = *(const float4*)&Br[k][tx * 4];
            accL[0][0] = fmaf(a.x, b.x, accL[0][0]); accL[0][1] = fmaf(a.x, b.y, accL[0][1]);
            accL[0][2] = fmaf(a.x, b.z, accL[0][2]); accL[0][3] = fmaf(a.x, b.w, accL[0][3]);
            accL[1][0] = fmaf(a.y, b.x, accL[1][0]); accL[1][1] = fmaf(a.y, b.y, accL[1][1]);
            accL[1][2] = fmaf(a.y, b.z, accL[1][2]); accL[1][3] = fmaf(a.y, b.w, accL[1][3]);
            accL[2][0] = fmaf(a.z, b.x, accL[2][0]); accL[2][1] = fmaf(a.z, b.y, accL[2][1]);
            accL[2][2] = fmaf(a.z, b.z, accL[2][2]); accL[2][3] = fmaf(a.z, b.w, accL[2][3]);
            accL[3][0] = fmaf(a.w, b.x, accL[3][0]); accL[3][1] = fmaf(a.w, b.y, accL[3][1]);
            accL[3][2] = fmaf(a.w, b.z, accL[3][2]); accL[3][3] = fmaf(a.w, b.w, accL[3][3]);
            accR[0][0] = fmaf(a.x, b2.x, accR[0][0]); accR[0][1] = fmaf(a.x, b2.y, accR[0][1]);
            accR[0][2] = fmaf(a.x, b2.z, accR[0][2]); accR[0][3] = fmaf(a.x, b2.w, accR[0][3]);
            accR[1][0] = fmaf(a.y, b2.x, accR[1][0]); accR[1][1] = fmaf(a.y, b2.y, accR[1][1]);
            accR[1][2] = fmaf(a.y, b2.z, accR[1][2]); accR[1][3] = fmaf(a.y, b2.w, accR[1][3]);
            accR[2][0] = fmaf(a.z, b2.x, accR[2][0]); accR[2][1] = fmaf(a.z, b2.y, accR[2][1]);
            accR[2][2] = fmaf(a.z, b2.z, accR[2][2]); accR[2][3] = fmaf(a.z, b2.w, accR[2][3]);
            accR[3][0] = fmaf(a.w, b2.x, accR[3][0]); accR[3][1] = fmaf(a.w, b2.y, accR[3][1]);
            accR[3][2] = fmaf(a.w, b2.z, accR[3][2]); accR[3][3] = fmaf(a.w, b2.w, accR[3][3]);
        }
        __syncthreads();
    }
    #pragma unroll
    for (int i = 0; i < 4; i++) {
        int row = row0 + ty * 4 + i;
        if (row >= NN) continue;
        int col = col0 + tx * 4;
        float4 vl, vr;
        vl.x = accL[i][0] + bl[col + 0]; vl.y = accL[i][1] + bl[col + 1];
        vl.z = accL[i][2] + bl[col + 2]; vl.w = accL[i][3] + bl[col + 3];
        vr.x = accR[i][0] + br[col + 0]; vr.y = accR[i][1] + br[col + 1];
        vr.z = accR[i][2] + br[col + 2]; vr.w = accR[i][3] + br[col + 3];
        *(float4*)&g_xl2[row * 256 + col] = vl;
        *(float4*)&g_xr2[row * 256 + col] = vr;
    }
}

// ================= layer-1 logits (warp per CSR slot, 4 heads) ==============
__global__ void logits1(const float* __restrict__ att) {
    int slot = (blockIdx.x * blockDim.x + threadIdx.x) >> 5;
    int lane = threadIdx.x & 31;
    if (slot >= ETOT) return;
    int src = g_csr_src[slot];
    int dst = g_csr_dst[slot];
    int c = lane * 8;
    const float4* pl = (const float4*)(g_xl1 + src * C1 + c);
    const float4* pr = (const float4*)(g_xr1 + dst * C1 + c);
    const float4* pa = (const float4*)(att + c);
    float p = 0.0f;
    #pragma unroll
    for (int j = 0; j < 2; j++) {
        float4 a = pl[j], b = pr[j], w = pa[j];
        p = fmaf(w.x, lrelu(a.x + b.x), p);
        p = fmaf(w.y, lrelu(a.y + b.y), p);
        p = fmaf(w.z, lrelu(a.z + b.z), p);
        p = fmaf(w.w, lrelu(a.w + b.w), p);
    }
    p += __shfl_down_sync(0xffffffffu, p, 4);
    p += __shfl_down_sync(0xffffffffu, p, 2);
    p += __shfl_down_sync(0xffffffffu, p, 1);
    if ((lane & 7) == 0) g_lw1[slot * 4 + (lane >> 3)] = p;
}

// ================= layer-1 softmax per node (warp/node, no atomics) =========
__global__ void softmax1() {
    int node = (blockIdx.x * blockDim.x + threadIdx.x) >> 5;
    int lane = threadIdx.x & 31;
    if (node >= NN) return;
    int s0 = g_off[node], s1 = g_off[node + 1];
    int sub = lane >> 2;        // 0..7 slot stride group
    int h = lane & 3;           // head
    float m = -INFINITY;
    for (int s = s0 + sub; s < s1; s += 8) m = fmaxf(m, g_lw1[s * 4 + h]);
    #pragma unroll
    for (int off = 16; off >= 4; off >>= 1)
        m = fmaxf(m, __shfl_xor_sync(0xffffffffu, m, off));
    float sum = 0.0f;
    for (int s = s0 + sub; s < s1; s += 8) sum += __expf(g_lw1[s * 4 + h] - m);
    #pragma unroll
    for (int off = 16; off >= 4; off >>= 1)
        sum += __shfl_xor_sync(0xffffffffu, sum, off);
    float inv = 1.0f / (sum + EPSS);
    for (int s = s0 + sub; s < s1; s += 8)
        g_lw1[s * 4 + h] = __expf(g_lw1[s * 4 + h] - m) * inv;
}

// ================= layer-1 aggregate (warp per node) + bias + ELU ===========
__global__ void aggregate1(const float* __restrict__ bias1) {
    int node = (blockIdx.x * blockDim.x + threadIdx.x) >> 5;
    int lane = threadIdx.x & 31;
    if (node >= NN) return;
    int s0 = g_off[node], s1 = g_off[node + 1];
    int h = lane >> 3;
    int c = lane * 8;
    float4 acc0 = make_float4(0.f, 0.f, 0.f, 0.f);
    float4 acc1 = make_float4(0.f, 0.f, 0.f, 0.f);
    for (int s = s0; s < s1; s++) {
        int src = g_csr_src[s];
        float alpha = g_lw1[s * 4 + h];
        const float4* p = (const float4*)(g_xl1 + src * C1 + c);
        float4 a0 = p[0], a1 = p[1];
        acc0.x = fmaf(alpha, a0.x, acc0.x); acc0.y = fmaf(alpha, a0.y, acc0.y);
        acc0.z = fmaf(alpha, a0.z, acc0.z); acc0.w = fmaf(alpha, a0.w, acc0.w);
        acc1.x = fmaf(alpha, a1.x, acc1.x); acc1.y = fmaf(alpha, a1.y, acc1.y);
        acc1.z = fmaf(alpha, a1.z, acc1.z); acc1.w = fmaf(alpha, a1.w, acc1.w);
    }
    const float4* pb = (const float4*)(bias1 + c);
    float4 b0 = pb[0], b1 = pb[1];
    float v[8] = { acc0.x + b0.x, acc0.y + b0.y, acc0.z + b0.z, acc0.w + b0.w,
                   acc1.x + b1.x, acc1.y + b1.y, acc1.z + b1.z, acc1.w + b1.w };
    float o[8];
    #pragma unroll
    for (int j = 0; j < 8; j++) o[j] = v[j] > 0.0f ? v[j] : expm1f(v[j]);
    float4* po = (float4*)(g_h + node * C1 + c);
    po[0] = make_float4(o[0], o[1], o[2], o[3]);
    po[1] = make_float4(o[4], o[5], o[6], o[7]);
}

// ================= layer-2 logits (warp per slot, 1 head) ===================
__global__ void logits2(const float* __restrict__ att) {
    int slot = (blockIdx.x * blockDim.x + threadIdx.x) >> 5;
    int lane = threadIdx.x & 31;
    if (slot >= ETOT) return;
    int src = g_csr_src[slot];
    int dst = g_csr_dst[slot];
    int c = lane * 8;
    const float4* pl = (const float4*)(g_xl2 + src * C1 + c);
    const float4* pr = (const float4*)(g_xr2 + dst * C1 + c);
    const float4* pa = (const float4*)(att + c);
    float p = 0.0f;
    #pragma unroll
    for (int j = 0; j < 2; j++) {
        float4 a = pl[j], b = pr[j], w = pa[j];
        p = fmaf(w.x, lrelu(a.x + b.x), p);
        p = fmaf(w.y, lrelu(a.y + b.y), p);
        p = fmaf(w.z, lrelu(a.z + b.z), p);
        p = fmaf(w.w, lrelu(a.w + b.w), p);
    }
    #pragma unroll
    for (int off = 16; off > 0; off >>= 1)
        p += __shfl_down_sync(0xffffffffu, p, off);
    if (lane == 0) g_lw2[slot] = p;
}

// ================= layer-2 softmax per node =================================
__global__ void softmax2() {
    int node = (blockIdx.x * blockDim.x + threadIdx.x) >> 5;
    int lane = threadIdx.x & 31;
    if (node >= NN) return;
    int s0 = g_off[node], s1 = g_off[node + 1];
    float m = -INFINITY;
    for (int s = s0 + lane; s < s1; s += 32) m = fmaxf(m, g_lw2[s]);
    #pragma unroll
    for (int off = 16; off > 0; off >>= 1)
        m = fmaxf(m, __shfl_xor_sync(0xffffffffu, m, off));
    float sum = 0.0f;
    for (int s = s0 + lane; s < s1; s += 32) sum += __expf(g_lw2[s] - m);
    #pragma unroll
    for (int off = 16; off > 0; off >>= 1)
        sum += __shfl_xor_sync(0xffffffffu, sum, off);
    float inv = 1.0f / (sum + EPSS);
    for (int s = s0 + lane; s < s1; s += 32)
        g_lw2[s] = __expf(g_lw2[s] - m) * inv;
}

// ================= layer-2 aggregate (warp per node) + bias2 ================
__global__ void aggregate2(const float* __restrict__ bias2,
                           float* __restrict__ out) {
    int node = (blockIdx.x * blockDim.x + threadIdx.x) >> 5;
    int lane = threadIdx.x & 31;
    if (node >= NN) return;
    int s0 = g_off[node], s1 = g_off[node + 1];
    int c = lane * 8;
    float4 acc0 = make_float4(0.f, 0.f, 0.f, 0.f);
    float4 acc1 = make_float4(0.f, 0.f, 0.f, 0.f);
    for (int s = s0; s < s1; s++) {
        int src = g_csr_src[s];
        float alpha = g_lw2[s];
        const float4* p = (const float4*)(g_xl2 + src * C1 + c);
        float4 a0 = p[0], a1 = p[1];
        acc0.x = fmaf(alpha, a0.x, acc0.x); acc0.y = fmaf(alpha, a0.y, acc0.y);
        acc0.z = fmaf(alpha, a0.z, acc0.z); acc0.w = fmaf(alpha, a0.w, acc0.w);
        acc1.x = fmaf(alpha, a1.x, acc1.x); acc1.y = fmaf(alpha, a1.y, acc1.y);
        acc1.z = fmaf(alpha, a1.z, acc1.z); acc1.w = fmaf(alpha, a1.w, acc1.w);
    }
    const float4* pb = (const float4*)(bias2 + c);
    float4 b0 = pb[0], b1 = pb[1];
    acc0.x += b0.x; acc0.y += b0.y; acc0.z += b0.z; acc0.w += b0.w;
    acc1.x += b1.x; acc1.y += b1.y; acc1.z += b1.z; acc1.w += b1.w;
    float4* po = (float4*)(out + node * C1 + c);
    po[0] = acc0;
    po[1] = acc1;
}

// ================= launcher =================================================
extern "C" void kernel_launch(void* const* d_in, const int* in_sizes, int n_in,
                              void* d_out, int out_size) {
    const float* x     = (const float*)d_in[0];
    const int*   ei    = (const int*)  d_in[1];
    const float* W_l1  = (const float*)d_in[2];
    const float* b_l1  = (const float*)d_in[3];
    const float* W_r1  = (const float*)d_in[4];
    const float* b_r1  = (const float*)d_in[5];
    const float* att1  = (const float*)d_in[6];
    const float* bias1 = (const float*)d_in[7];
    const float* W_l2  = (const float*)d_in[8];
    const float* b_l2  = (const float*)d_in[9];
    const float* W_r2  = (const float*)d_in[10];
    const float* b_r2  = (const float*)d_in[11];
    const float* att2  = (const float*)d_in[12];
    const float* bias2 = (const float*)d_in[13];
    float* out = (float*)d_out;

    const int T = 256;
    int blkN    = (NN + T - 1) / T;
    int blkE    = (ETOT + T - 1) / T;
    int blkSlot = (ETOT + 7) / 8;      // warp per CSR slot
    int blkNode = (NN + 7) / 8;        // warp per node
    int blkG1   = (NN + 15) / 16;

    // CSR build
    zero_deg<<<blkN, T>>>();
    csr_count<<<blkE, T>>>(ei);
    csr_scan<<<1, 1024>>>();
    csr_scatter<<<blkE, T>>>(ei);

    // layer 1
    gemm1_kernel<<<blkG1, T>>>(x, W_l1, b_l1, W_r1, b_r1);
    logits1<<<blkSlot, T>>>(att1);
    softmax1<<<blkNode, T>>>();
    aggregate1<<<blkNode, T>>>(bias1);

    // layer 2
    dim3 g2((NN + 63) / 64, 4);
    gemm_dual<<<g2, T>>>(W_l2, b_l2, W_r2, b_r2);
    logits2<<<blkSlot, T>>>(att2);
    softmax2<<<blkNode, T>>>();
    aggregate2<<<blkNode, T>>>(bias2, out);
}

// round 4
// speedup vs baseline: 2.3888x; 1.0044x over previous
#include <cuda_runtime.h>
#include <math.h>

#define NN    50000
#define EE    400000
#define ETOT  (NN + EE)
#define C1    256
#define KIN   20
#define NEG_SLOPE 0.2f
#define EPSS  1e-16f

// ---------------- scratch (static device globals; no allocations) ----------
__device__ float g_xl1[NN * C1];
__device__ float g_xr1[NN * C1];
__device__ float g_h[NN * C1];      // ELU(layer-1 output)
__device__ float g_xl2[NN * C1];
__device__ float g_xr2[NN * C1];
__device__ float g_lw1[ETOT * 4];   // logits -> normalized alpha (layer 1)
__device__ float g_lw2[ETOT];       // logits -> normalized alpha (layer 2)
__device__ int   g_deg[NN];         // degree counts, then scatter cursor
__device__ int   g_off[NN + 1];     // CSR offsets
__device__ int   g_csr_src[ETOT];
__device__ int   g_csr_dst[ETOT];

__device__ __forceinline__ float lrelu(float v) {
    return v > 0.0f ? v : NEG_SLOPE * v;
}

// ---- packed f32x2 (FFMA2) helpers ----
__device__ __forceinline__ unsigned long long pack2(float lo, float hi) {
    unsigned long long r;
    asm("mov.b64 %0, {%1, %2};" : "=l"(r) : "f"(lo), "f"(hi));
    return r;
}
__device__ __forceinline__ unsigned long long fma2(unsigned long long a,
                                                   unsigned long long b,
                                                   unsigned long long c) {
    unsigned long long d;
    asm("fma.rn.f32x2 %0, %1, %2, %3;" : "=l"(d) : "l"(a), "l"(b), "l"(c));
    return d;
}
__device__ __forceinline__ float2 unpack2(unsigned long long v) {
    float lo, hi;
    asm("mov.b64 {%0, %1}, %2;" : "=f"(lo), "=f"(hi) : "l"(v));
    return make_float2(lo, hi);
}

// ================= CSR construction =================
__global__ void zero_deg() {
    int i = blockIdx.x * blockDim.x + threadIdx.x;
    if (i < NN) g_deg[i] = 0;
}

__global__ void csr_count(const int* __restrict__ ei) {
    int e = blockIdx.x * blockDim.x + threadIdx.x;
    if (e >= ETOT) return;
    int dst = (e < EE) ? ei[EE + e] : e - EE;
    atomicAdd(&g_deg[dst], 1);
}

// single-block exclusive scan over g_deg -> g_off; also zeroes g_deg (cursor)
__global__ void csr_scan() {
    int tid = threadIdx.x;
    int lane = tid & 31, wid = tid >> 5;
    __shared__ int wsum[32];
    __shared__ int carry_s;
    if (tid == 0) carry_s = 0;
    __syncthreads();
    for (int base = 0; base < NN; base += 1024) {
        __syncthreads();
        int i = base + tid;
        int v = (i < NN) ? g_deg[i] : 0;
        if (i < NN) g_deg[i] = 0;
        int x = v;
        #pragma unroll
        for (int o = 1; o < 32; o <<= 1) {
            int y = __shfl_up_sync(0xffffffffu, x, o);
            if (lane >= o) x += y;
        }
        if (lane == 31) wsum[wid] = x;
        __syncthreads();
        if (wid == 0) {
            int w = wsum[lane];
            #pragma unroll
            for (int o = 1; o < 32; o <<= 1) {
                int y = __shfl_up_sync(0xffffffffu, w, o);
                if (lane >= o) w += y;
            }
            wsum[lane] = w;
        }
        __syncthreads();
        int blockincl = x + (wid > 0 ? wsum[wid - 1] : 0);
        int excl = carry_s + blockincl - v;
        if (i < NN) g_off[i] = excl;
        __syncthreads();
        if (tid == 1023) carry_s += blockincl;
    }
    __syncthreads();
    if (tid == 0) g_off[NN] = carry_s;
}

__global__ void csr_scatter(const int* __restrict__ ei) {
    int e = blockIdx.x * blockDim.x + threadIdx.x;
    if (e >= ETOT) return;
    int src, dst;
    if (e < EE) { src = ei[e]; dst = ei[EE + e]; }
    else        { src = dst = e - EE; }
    int pos = g_off[dst] + atomicAdd(&g_deg[dst], 1);
    g_csr_src[pos] = src;
    g_csr_dst[pos] = dst;
}

// ================= layer-1 GEMM: x[N,20]@W[20,256]+b (two outputs) =========
__global__ void gemm1_kernel(const float* __restrict__ x,
                             const float* __restrict__ Wl, const float* __restrict__ bl,
                             const float* __restrict__ Wr, const float* __restrict__ br) {
    __shared__ float swl[KIN * 256];
    __shared__ float swr[KIN * 256];
    __shared__ float sx[16][KIN];
    int tid = threadIdx.x;
    for (int i = tid; i < KIN * 256; i += 256) { swl[i] = Wl[i]; swr[i] = Wr[i]; }
    int nb = blockIdx.x * 16;
    for (int i = tid; i < 16 * KIN; i += 256) {
        int node = nb + i / KIN;
        sx[i / KIN][i % KIN] = (node < NN) ? x[node * KIN + (i % KIN)] : 0.0f;
    }
    __syncthreads();
    float bL = bl[tid], bR = br[tid];
    for (int i = 0; i < 16; i++) {
        int node = nb + i;
        if (node >= NN) break;
        float al = bL, ar = bR;
        #pragma unroll
        for (int k = 0; k < KIN; k++) {
            float xv = sx[i][k];
            al = fmaf(xv, swl[k * 256 + tid], al);
            ar = fmaf(xv, swr[k * 256 + tid], ar);
        }
        g_xl1[node * 256 + tid] = al;
        g_xr1[node * 256 + tid] = ar;
    }
}

// ================= dual layer-2 GEMM with packed f32x2 FMAs =================
// g_h[N,256] @ {W_l2, W_r2} -> g_xl2, g_xr2 ; 64x64 tile, 256 threads,
// per-thread 4 rows x 4 cols x 2 matrices, accumulated as f32x2 pairs.
__global__ void gemm_dual(const float* __restrict__ Wl, const float* __restrict__ bl,
                          const float* __restrict__ Wr, const float* __restrict__ br) {
    const float* __restrict__ A = g_h;
    __shared__ float As[16][64];
    __shared__ float Bl[16][64];
    __shared__ float Br[16][64];
    int tid = threadIdx.x;
    int tx = tid & 15;
    int ty = tid >> 4;
    int row0 = blockIdx.x * 64;
    int col0 = blockIdx.y * 64;

    unsigned long long accL[4][2], accR[4][2];
    #pragma unroll
    for (int i = 0; i < 4; i++) {
        accL[i][0] = 0ull; accL[i][1] = 0ull;
        accR[i][0] = 0ull; accR[i][1] = 0ull;
    }

    for (int kt = 0; kt < 256; kt += 16) {
        #pragma unroll
        for (int j = 0; j < 4; j++) {
            int i = tid + j * 256;
            int m = i >> 4, k = i & 15;
            int row = row0 + m;
            As[k][m] = (row < NN) ? A[row * 256 + kt + k] : 0.0f;
        }
        #pragma unroll
        for (int j = 0; j < 4; j++) {
            int i = tid + j * 256;
            int k = i >> 6, col = i & 63;
            Bl[k][col] = Wl[(kt + k) * 256 + col0 + col];
            Br[k][col] = Wr[(kt + k) * 256 + col0 + col];
        }
        __syncthreads();
        #pragma unroll
        for (int k = 0; k < 16; k++) {
            float4 a = *(const float4*)&As[k][ty * 4];
            ulonglong2 b  = *(const ulonglong2*)&Bl[k][tx * 4];
            ulonglong2 b2 = *(const ulonglong2*)&Br[k][tx * 4];
            unsigned long long ap0 = pack2(a.x, a.x);
            unsigned long long ap1 = pack2(a.y, a.y);
            unsigned long long ap2 = pack2(a.z, a.z);
            unsigned long long ap3 = pack2(a.w, a.w);
            accL[0][0] = fma2(ap0, b.x, accL[0][0]); accL[0][1] = fma2(ap0, b.y, accL[0][1]);
            accL[1][0] = fma2(ap1, b.x, accL[1][0]); accL[1][1] = fma2(ap1, b.y, accL[1][1]);
            accL[2][0] = fma2(ap2, b.x, accL[2][0]); accL[2][1] = fma2(ap2, b.y, accL[2][1]);
            accL[3][0] = fma2(ap3, b.x, accL[3][0]); accL[3][1] = fma2(ap3, b.y, accL[3][1]);
            accR[0][0] = fma2(ap0, b2.x, accR[0][0]); accR[0][1] = fma2(ap0, b2.y, accR[0][1]);
            accR[1][0] = fma2(ap1, b2.x, accR[1][0]); accR[1][1] = fma2(ap1, b2.y, accR[1][1]);
            accR[2][0] = fma2(ap2, b2.x, accR[2][0]); accR[2][1] = fma2(ap2, b2.y, accR[2][1]);
            accR[3][0] = fma2(ap3, b2.x, accR[3][0]); accR[3][1] = fma2(ap3, b2.y, accR[3][1]);
        }
        __syncthreads();
    }
    #pragma unroll
    for (int i = 0; i < 4; i++) {
        int row = row0 + ty * 4 + i;
        if (row >= NN) continue;
        int col = col0 + tx * 4;
        float2 l0 = unpack2(accL[i][0]), l1 = unpack2(accL[i][1]);
        float2 r0 = unpack2(accR[i][0]), r1 = unpack2(accR[i][1]);
        float4 vl, vr;
        vl.x = l0.x + bl[col + 0]; vl.y = l0.y + bl[col + 1];
        vl.z = l1.x + bl[col + 2]; vl.w = l1.y + bl[col + 3];
        vr.x = r0.x + br[col + 0]; vr.y = r0.y + br[col + 1];
        vr.z = r1.x + br[col + 2]; vr.w = r1.y + br[col + 3];
        *(float4*)&g_xl2[row * 256 + col] = vl;
        *(float4*)&g_xr2[row * 256 + col] = vr;
    }
}

// ================= layer-1 logits (warp per CSR slot, 4 heads) ==============
__global__ void logits1(const float* __restrict__ att) {
    int slot = (blockIdx.x * blockDim.x + threadIdx.x) >> 5;
    int lane = threadIdx.x & 31;
    if (slot >= ETOT) return;
    int src = g_csr_src[slot];
    int dst = g_csr_dst[slot];
    int c = lane * 8;
    const float4* pl = (const float4*)(g_xl1 + src * C1 + c);
    const float4* pr = (const float4*)(g_xr1 + dst * C1 + c);
    const float4* pa = (const float4*)(att + c);
    float p = 0.0f;
    #pragma unroll
    for (int j = 0; j < 2; j++) {
        float4 a = pl[j], b = pr[j], w = pa[j];
        p = fmaf(w.x, lrelu(a.x + b.x), p);
        p = fmaf(w.y, lrelu(a.y + b.y), p);
        p = fmaf(w.z, lrelu(a.z + b.z), p);
        p = fmaf(w.w, lrelu(a.w + b.w), p);
    }
    p += __shfl_down_sync(0xffffffffu, p, 4);
    p += __shfl_down_sync(0xffffffffu, p, 2);
    p += __shfl_down_sync(0xffffffffu, p, 1);
    if ((lane & 7) == 0) g_lw1[slot * 4 + (lane >> 3)] = p;
}

// ================= layer-1 softmax per node (warp/node, no atomics) =========
__global__ void softmax1() {
    int node = (blockIdx.x * blockDim.x + threadIdx.x) >> 5;
    int lane = threadIdx.x & 31;
    if (node >= NN) return;
    int s0 = g_off[node], s1 = g_off[node + 1];
    int sub = lane >> 2;        // 0..7 slot stride group
    int h = lane & 3;           // head
    float m = -INFINITY;
    for (int s = s0 + sub; s < s1; s += 8) m = fmaxf(m, g_lw1[s * 4 + h]);
    #pragma unroll
    for (int off = 16; off >= 4; off >>= 1)
        m = fmaxf(m, __shfl_xor_sync(0xffffffffu, m, off));
    float sum = 0.0f;
    for (int s = s0 + sub; s < s1; s += 8) sum += __expf(g_lw1[s * 4 + h] - m);
    #pragma unroll
    for (int off = 16; off >= 4; off >>= 1)
        sum += __shfl_xor_sync(0xffffffffu, sum, off);
    float inv = 1.0f / (sum + EPSS);
    for (int s = s0 + sub; s < s1; s += 8)
        g_lw1[s * 4 + h] = __expf(g_lw1[s * 4 + h] - m) * inv;
}

// ================= layer-1 aggregate (warp per node) + bias + ELU ===========
__global__ void aggregate1(const float* __restrict__ bias1) {
    int node = (blockIdx.x * blockDim.x + threadIdx.x) >> 5;
    int lane = threadIdx.x & 31;
    if (node >= NN) return;
    int s0 = g_off[node], s1 = g_off[node + 1];
    int h = lane >> 3;
    int c = lane * 8;
    float4 acc0 = make_float4(0.f, 0.f, 0.f, 0.f);
    float4 acc1 = make_float4(0.f, 0.f, 0.f, 0.f);
    for (int s = s0; s < s1; s++) {
        int src = g_csr_src[s];
        float alpha = g_lw1[s * 4 + h];
        const float4* p = (const float4*)(g_xl1 + src * C1 + c);
        float4 a0 = p[0], a1 = p[1];
        acc0.x = fmaf(alpha, a0.x, acc0.x); acc0.y = fmaf(alpha, a0.y, acc0.y);
        acc0.z = fmaf(alpha, a0.z, acc0.z); acc0.w = fmaf(alpha, a0.w, acc0.w);
        acc1.x = fmaf(alpha, a1.x, acc1.x); acc1.y = fmaf(alpha, a1.y, acc1.y);
        acc1.z = fmaf(alpha, a1.z, acc1.z); acc1.w = fmaf(alpha, a1.w, acc1.w);
    }
    const float4* pb = (const float4*)(bias1 + c);
    float4 b0 = pb[0], b1 = pb[1];
    float v[8] = { acc0.x + b0.x, acc0.y + b0.y, acc0.z + b0.z, acc0.w + b0.w,
                   acc1.x + b1.x, acc1.y + b1.y, acc1.z + b1.z, acc1.w + b1.w };
    float o[8];
    #pragma unroll
    for (int j = 0; j < 8; j++) o[j] = v[j] > 0.0f ? v[j] : expm1f(v[j]);
    float4* po = (float4*)(g_h + node * C1 + c);
    po[0] = make_float4(o[0], o[1], o[2], o[3]);
    po[1] = make_float4(o[4], o[5], o[6], o[7]);
}

// ================= layer-2 logits (warp per slot, 1 head) ===================
__global__ void logits2(const float* __restrict__ att) {
    int slot = (blockIdx.x * blockDim.x + threadIdx.x) >> 5;
    int lane = threadIdx.x & 31;
    if (slot >= ETOT) return;
    int src = g_csr_src[slot];
    int dst = g_csr_dst[slot];
    int c = lane * 8;
    const float4* pl = (const float4*)(g_xl2 + src * C1 + c);
    const float4* pr = (const float4*)(g_xr2 + dst * C1 + c);
    const float4* pa = (const float4*)(att + c);
    float p = 0.0f;
    #pragma unroll
    for (int j = 0; j < 2; j++) {
        float4 a = pl[j], b = pr[j], w = pa[j];
        p = fmaf(w.x, lrelu(a.x + b.x), p);
        p = fmaf(w.y, lrelu(a.y + b.y), p);
        p = fmaf(w.z, lrelu(a.z + b.z), p);
        p = fmaf(w.w, lrelu(a.w + b.w), p);
    }
    #pragma unroll
    for (int off = 16; off > 0; off >>= 1)
        p += __shfl_down_sync(0xffffffffu, p, off);
    if (lane == 0) g_lw2[slot] = p;
}

// ================= layer-2 softmax per node =================================
__global__ void softmax2() {
    int node = (blockIdx.x * blockDim.x + threadIdx.x) >> 5;
    int lane = threadIdx.x & 31;
    if (node >= NN) return;
    int s0 = g_off[node], s1 = g_off[node + 1];
    float m = -INFINITY;
    for (int s = s0 + lane; s < s1; s += 32) m = fmaxf(m, g_lw2[s]);
    #pragma unroll
    for (int off = 16; off > 0; off >>= 1)
        m = fmaxf(m, __shfl_xor_sync(0xffffffffu, m, off));
    float sum = 0.0f;
    for (int s = s0 + lane; s < s1; s += 32) sum += __expf(g_lw2[s] - m);
    #pragma unroll
    for (int off = 16; off > 0; off >>= 1)
        sum += __shfl_xor_sync(0xffffffffu, sum, off);
    float inv = 1.0f / (sum + EPSS);
    for (int s = s0 + lane; s < s1; s += 32)
        g_lw2[s] = __expf(g_lw2[s] - m) * inv;
}

// ================= layer-2 aggregate (warp per node) + bias2 ================
__global__ void aggregate2(const float* __restrict__ bias2,
                           float* __restrict__ out) {
    int node = (blockIdx.x * blockDim.x + threadIdx.x) >> 5;
    int lane = threadIdx.x & 31;
    if (node >= NN) return;
    int s0 = g_off[node], s1 = g_off[node + 1];
    int c = lane * 8;
    float4 acc0 = make_float4(0.f, 0.f, 0.f, 0.f);
    float4 acc1 = make_float4(0.f, 0.f, 0.f, 0.f);
    for (int s = s0; s < s1; s++) {
        int src = g_csr_src[s];
        float alpha = g_lw2[s];
        const float4* p = (const float4*)(g_xl2 + src * C1 + c);
        float4 a0 = p[0], a1 = p[1];
        acc0.x = fmaf(alpha, a0.x, acc0.x); acc0.y = fmaf(alpha, a0.y, acc0.y);
        acc0.z = fmaf(alpha, a0.z, acc0.z); acc0.w = fmaf(alpha, a0.w, acc0.w);
        acc1.x = fmaf(alpha, a1.x, acc1.x); acc1.y = fmaf(alpha, a1.y, acc1.y);
        acc1.z = fmaf(alpha, a1.z, acc1.z); acc1.w = fmaf(alpha, a1.w, acc1.w);
    }
    const float4* pb = (const float4*)(bias2 + c);
    float4 b0 = pb[0], b1 = pb[1];
    acc0.x += b0.x; acc0.y += b0.y; acc0.z += b0.z; acc0.w += b0.w;
    acc1.x += b1.x; acc1.y += b1.y; acc1.z += b1.z; acc1.w += b1.w;
    float4* po = (float4*)(out + node * C1 + c);
    po[0] = acc0;
    po[1] = acc1;
}

// ================= launcher =================================================
extern "C" void kernel_launch(void* const* d_in, const int* in_sizes, int n_in,
                              void* d_out, int out_size) {
    const float* x     = (const float*)d_in[0];
    const int*   ei    = (const int*)  d_in[1];
    const float* W_l1  = (const float*)d_in[2];
    const float* b_l1  = (const float*)d_in[3];
    const float* W_r1  = (const float*)d_in[4];
    const float* b_r1  = (const float*)d_in[5];
    const float* att1  = (const float*)d_in[6];
    const float* bias1 = (const float*)d_in[7];
    const float* W_l2  = (const float*)d_in[8];
    const float* b_l2  = (const float*)d_in[9];
    const float* W_r2  = (const float*)d_in[10];
    const float* b_r2  = (const float*)d_in[11];
    const float* att2  = (const float*)d_in[12];
    const float* bias2 = (const float*)d_in[13];
    float* out = (float*)d_out;

    const int T = 256;
    int blkN    = (NN + T - 1) / T;
    int blkE    = (ETOT + T - 1) / T;
    int blkSlot = (ETOT + 7) / 8;      // warp per CSR slot
    int blkNode = (NN + 7) / 8;        // warp per node
    int blkG1   = (NN + 15) / 16;

    // CSR build
    zero_deg<<<blkN, T>>>();
    csr_count<<<blkE, T>>>(ei);
    csr_scan<<<1, 1024>>>();
    csr_scatter<<<blkE, T>>>(ei);

    // layer 1
    gemm1_kernel<<<blkG1, T>>>(x, W_l1, b_l1, W_r1, b_r1);
    logits1<<<blkSlot, T>>>(att1);
    softmax1<<<blkNode, T>>>();
    aggregate1<<<blkNode, T>>>(bias1);

    // layer 2
    dim3 g2((NN + 63) / 64, 4);
    gemm_dual<<<g2, T>>>(W_l2, b_l2, W_r2, b_r2);
    logits2<<<blkSlot, T>>>(att2);
    softmax2<<<blkNode, T>>>();
    aggregate2<<<blkNode, T>>>(bias2, out);
}

// round 5
// speedup vs baseline: 2.9028x; 1.2152x over previous
#include <cuda_runtime.h>
#include <math.h>

#define NN    50000
#define EE    400000
#define ETOT  (NN + EE)
#define C1    256
#define KIN   20
#define NEG_SLOPE 0.2f
#define EPSS  1e-16f

// ---------------- scratch (static device globals; no allocations) ----------
__device__ float g_xl1[NN * C1];
__device__ float g_xr1[NN * C1];
__device__ float g_h[NN * C1];      // ELU(layer-1 output)
__device__ float g_xl2[NN * C1];
__device__ float g_xr2[NN * C1];
__device__ int   g_deg[NN];         // degree counts, then scatter cursor
__device__ int   g_off[NN + 1];     // CSR offsets
__device__ int   g_csr_src[ETOT];

__device__ __forceinline__ float lrelu(float v) {
    return v > 0.0f ? v : NEG_SLOPE * v;
}

// ---- packed f32x2 (FFMA2) helpers ----
__device__ __forceinline__ unsigned long long pack2(float lo, float hi) {
    unsigned long long r;
    asm("mov.b64 %0, {%1, %2};" : "=l"(r) : "f"(lo), "f"(hi));
    return r;
}
__device__ __forceinline__ unsigned long long fma2(unsigned long long a,
                                                   unsigned long long b,
                                                   unsigned long long c) {
    unsigned long long d;
    asm("fma.rn.f32x2 %0, %1, %2, %3;" : "=l"(d) : "l"(a), "l"(b), "l"(c));
    return d;
}
__device__ __forceinline__ float2 unpack2(unsigned long long v) {
    float lo, hi;
    asm("mov.b64 {%0, %1}, %2;" : "=f"(lo), "=f"(hi) : "l"(v));
    return make_float2(lo, hi);
}

// ================= CSR construction =================
__global__ void zero_deg() {
    int i = blockIdx.x * blockDim.x + threadIdx.x;
    if (i < NN) g_deg[i] = 0;
}

__global__ void csr_count(const int* __restrict__ ei) {
    int e = blockIdx.x * blockDim.x + threadIdx.x;
    if (e >= ETOT) return;
    int dst = (e < EE) ? ei[EE + e] : e - EE;
    atomicAdd(&g_deg[dst], 1);
}

// single-block exclusive scan over g_deg -> g_off; also zeroes g_deg (cursor)
__global__ void csr_scan() {
    int tid = threadIdx.x;
    int lane = tid & 31, wid = tid >> 5;
    __shared__ int wsum[32];
    __shared__ int carry_s;
    if (tid == 0) carry_s = 0;
    __syncthreads();
    for (int base = 0; base < NN; base += 1024) {
        __syncthreads();
        int i = base + tid;
        int v = (i < NN) ? g_deg[i] : 0;
        if (i < NN) g_deg[i] = 0;
        int x = v;
        #pragma unroll
        for (int o = 1; o < 32; o <<= 1) {
            int y = __shfl_up_sync(0xffffffffu, x, o);
            if (lane >= o) x += y;
        }
        if (lane == 31) wsum[wid] = x;
        __syncthreads();
        if (wid == 0) {
            int w = wsum[lane];
            #pragma unroll
            for (int o = 1; o < 32; o <<= 1) {
                int y = __shfl_up_sync(0xffffffffu, w, o);
                if (lane >= o) w += y;
            }
            wsum[lane] = w;
        }
        __syncthreads();
        int blockincl = x + (wid > 0 ? wsum[wid - 1] : 0);
        int excl = carry_s + blockincl - v;
        if (i < NN) g_off[i] = excl;
        __syncthreads();
        if (tid == 1023) carry_s += blockincl;
    }
    __syncthreads();
    if (tid == 0) g_off[NN] = carry_s;
}

__global__ void csr_scatter(const int* __restrict__ ei) {
    int e = blockIdx.x * blockDim.x + threadIdx.x;
    if (e >= ETOT) return;
    int src, dst;
    if (e < EE) { src = ei[e]; dst = ei[EE + e]; }
    else        { src = dst = e - EE; }
    int pos = g_off[dst] + atomicAdd(&g_deg[dst], 1);
    g_csr_src[pos] = src;
}

// ================= layer-1 GEMM: x[N,20]@W[20,256]+b (two outputs) =========
__global__ void gemm1_kernel(const float* __restrict__ x,
                             const float* __restrict__ Wl, const float* __restrict__ bl,
                             const float* __restrict__ Wr, const float* __restrict__ br) {
    __shared__ float swl[KIN * 256];
    __shared__ float swr[KIN * 256];
    __shared__ float sx[16][KIN];
    int tid = threadIdx.x;
    for (int i = tid; i < KIN * 256; i += 256) { swl[i] = Wl[i]; swr[i] = Wr[i]; }
    int nb = blockIdx.x * 16;
    for (int i = tid; i < 16 * KIN; i += 256) {
        int node = nb + i / KIN;
        sx[i / KIN][i % KIN] = (node < NN) ? x[node * KIN + (i % KIN)] : 0.0f;
    }
    __syncthreads();
    float bL = bl[tid], bR = br[tid];
    for (int i = 0; i < 16; i++) {
        int node = nb + i;
        if (node >= NN) break;
        float al = bL, ar = bR;
        #pragma unroll
        for (int k = 0; k < KIN; k++) {
            float xv = sx[i][k];
            al = fmaf(xv, swl[k * 256 + tid], al);
            ar = fmaf(xv, swr[k * 256 + tid], ar);
        }
        g_xl1[node * 256 + tid] = al;
        g_xr1[node * 256 + tid] = ar;
    }
}

// ================= dual layer-2 GEMM with packed f32x2 FMAs =================
__global__ void gemm_dual(const float* __restrict__ Wl, const float* __restrict__ bl,
                          const float* __restrict__ Wr, const float* __restrict__ br) {
    const float* __restrict__ A = g_h;
    __shared__ float As[16][64];
    __shared__ float Bl[16][64];
    __shared__ float Br[16][64];
    int tid = threadIdx.x;
    int tx = tid & 15;
    int ty = tid >> 4;
    int row0 = blockIdx.x * 64;
    int col0 = blockIdx.y * 64;

    unsigned long long accL[4][2], accR[4][2];
    #pragma unroll
    for (int i = 0; i < 4; i++) {
        accL[i][0] = 0ull; accL[i][1] = 0ull;
        accR[i][0] = 0ull; accR[i][1] = 0ull;
    }

    for (int kt = 0; kt < 256; kt += 16) {
        #pragma unroll
        for (int j = 0; j < 4; j++) {
            int i = tid + j * 256;
            int m = i >> 4, k = i & 15;
            int row = row0 + m;
            As[k][m] = (row < NN) ? A[row * 256 + kt + k] : 0.0f;
        }
        #pragma unroll
        for (int j = 0; j < 4; j++) {
            int i = tid + j * 256;
            int k = i >> 6, col = i & 63;
            Bl[k][col] = Wl[(kt + k) * 256 + col0 + col];
            Br[k][col] = Wr[(kt + k) * 256 + col0 + col];
        }
        __syncthreads();
        #pragma unroll
        for (int k = 0; k < 16; k++) {
            float4 a = *(const float4*)&As[k][ty * 4];
            ulonglong2 b  = *(const ulonglong2*)&Bl[k][tx * 4];
            ulonglong2 b2 = *(const ulonglong2*)&Br[k][tx * 4];
            unsigned long long ap0 = pack2(a.x, a.x);
            unsigned long long ap1 = pack2(a.y, a.y);
            unsigned long long ap2 = pack2(a.z, a.z);
            unsigned long long ap3 = pack2(a.w, a.w);
            accL[0][0] = fma2(ap0, b.x, accL[0][0]); accL[0][1] = fma2(ap0, b.y, accL[0][1]);
            accL[1][0] = fma2(ap1, b.x, accL[1][0]); accL[1][1] = fma2(ap1, b.y, accL[1][1]);
            accL[2][0] = fma2(ap2, b.x, accL[2][0]); accL[2][1] = fma2(ap2, b.y, accL[2][1]);
            accL[3][0] = fma2(ap3, b.x, accL[3][0]); accL[3][1] = fma2(ap3, b.y, accL[3][1]);
            accR[0][0] = fma2(ap0, b2.x, accR[0][0]); accR[0][1] = fma2(ap0, b2.y, accR[0][1]);
            accR[1][0] = fma2(ap1, b2.x, accR[1][0]); accR[1][1] = fma2(ap1, b2.y, accR[1][1]);
            accR[2][0] = fma2(ap2, b2.x, accR[2][0]); accR[2][1] = fma2(ap2, b2.y, accR[2][1]);
            accR[3][0] = fma2(ap3, b2.x, accR[3][0]); accR[3][1] = fma2(ap3, b2.y, accR[3][1]);
        }
        __syncthreads();
    }
    #pragma unroll
    for (int i = 0; i < 4; i++) {
        int row = row0 + ty * 4 + i;
        if (row >= NN) continue;
        int col = col0 + tx * 4;
        float2 l0 = unpack2(accL[i][0]), l1 = unpack2(accL[i][1]);
        float2 r0 = unpack2(accR[i][0]), r1 = unpack2(accR[i][1]);
        float4 vl, vr;
        vl.x = l0.x + bl[col + 0]; vl.y = l0.y + bl[col + 1];
        vl.z = l1.x + bl[col + 2]; vl.w = l1.y + bl[col + 3];
        vr.x = r0.x + br[col + 0]; vr.y = r0.y + br[col + 1];
        vr.z = r1.x + br[col + 2]; vr.w = r1.y + br[col + 3];
        *(float4*)&g_xl2[row * 256 + col] = vl;
        *(float4*)&g_xr2[row * 256 + col] = vr;
    }
}

// ================= fused edge pass: logits + online softmax + aggregate =====
// LAYER=1: xl=g_xl1, xr=g_xr1, out=g_h (bias1 + ELU), 4 heads (8-lane groups)
// LAYER=2: xl=g_xl2, xr=g_xr2, out=d_out (bias2), 1 head (32-lane reduce)
// Warp per node. Each lane owns 8 channels (c = lane*8).
template<int LAYER>
__global__ void fused_edge(const float* __restrict__ att,
                           const float* __restrict__ bias,
                           float* __restrict__ out_arg) {
    const float* __restrict__ xl = (LAYER == 1) ? g_xl1 : g_xl2;
    const float* __restrict__ xr = (LAYER == 1) ? g_xr1 : g_xr2;

    int node = (blockIdx.x * blockDim.x + threadIdx.x) >> 5;
    int lane = threadIdx.x & 31;
    if (node >= NN) return;
    int s0 = g_off[node], s1 = g_off[node + 1];
    int c = lane * 8;

    // resident per-node data
    const float4* pr = (const float4*)(xr + node * C1 + c);
    float4 r0 = pr[0], r1 = pr[1];
    const float4* pa = (const float4*)(att + c);
    float4 w0 = pa[0], w1 = pa[1];

    // online softmax state (replicated within head group)
    float m = -INFINITY, ssum = 0.0f;
    float4 acc0 = make_float4(0.f, 0.f, 0.f, 0.f);
    float4 acc1 = make_float4(0.f, 0.f, 0.f, 0.f);

    // software-pipelined edge loop: prefetch next src row
    int src = g_csr_src[s0];
    const float4* pl = (const float4*)(xl + src * C1 + c);
    float4 l0 = pl[0], l1 = pl[1];

    for (int s = s0; s < s1; s++) {
        float4 c0 = l0, c1 = l1;
        if (s + 1 < s1) {
            int nsrc = g_csr_src[s + 1];
            const float4* pn = (const float4*)(xl + nsrc * C1 + c);
            l0 = pn[0], l1 = pn[1];
        }
        // logit contribution of this lane's 8 channels
        float p;
        p  =        w0.x * lrelu(c0.x + r0.x);
        p = fmaf(w0.y, lrelu(c0.y + r0.y), p);
        p = fmaf(w0.z, lrelu(c0.z + r0.z), p);
        p = fmaf(w0.w, lrelu(c0.w + r0.w), p);
        p = fmaf(w1.x, lrelu(c1.x + r1.x), p);
        p = fmaf(w1.y, lrelu(c1.y + r1.y), p);
        p = fmaf(w1.z, lrelu(c1.z + r1.z), p);
        p = fmaf(w1.w, lrelu(c1.w + r1.w), p);
        // reduce to full logit
        if (LAYER == 1) {
            // 4 heads: reduce within 8-lane group, all 8 lanes get result
            p += __shfl_xor_sync(0xffffffffu, p, 4);
            p += __shfl_xor_sync(0xffffffffu, p, 2);
            p += __shfl_xor_sync(0xffffffffu, p, 1);
        } else {
            #pragma unroll
            for (int off = 16; off > 0; off >>= 1)
                p += __shfl_xor_sync(0xffffffffu, p, off);
        }
        // online softmax update
        if (p > m) {
            float sc = __expf(m - p);       // exp(-inf)=0 on first edge
            ssum *= sc;
            acc0.x *= sc; acc0.y *= sc; acc0.z *= sc; acc0.w *= sc;
            acc1.x *= sc; acc1.y *= sc; acc1.z *= sc; acc1.w *= sc;
            m = p;
        }
        float wgt = __expf(p - m);
        ssum += wgt;
        acc0.x = fmaf(wgt, c0.x, acc0.x); acc0.y = fmaf(wgt, c0.y, acc0.y);
        acc0.z = fmaf(wgt, c0.z, acc0.z); acc0.w = fmaf(wgt, c0.w, acc0.w);
        acc1.x = fmaf(wgt, c1.x, acc1.x); acc1.y = fmaf(wgt, c1.y, acc1.y);
        acc1.z = fmaf(wgt, c1.z, acc1.z); acc1.w = fmaf(wgt, c1.w, acc1.w);
    }

    float inv = 1.0f / (ssum + EPSS);
    const float4* pb = (const float4*)(bias + c);
    float4 b0 = pb[0], b1 = pb[1];
    float v[8] = { acc0.x * inv + b0.x, acc0.y * inv + b0.y,
                   acc0.z * inv + b0.z, acc0.w * inv + b0.w,
                   acc1.x * inv + b1.x, acc1.y * inv + b1.y,
                   acc1.z * inv + b1.z, acc1.w * inv + b1.w };
    if (LAYER == 1) {
        #pragma unroll
        for (int j = 0; j < 8; j++) v[j] = v[j] > 0.0f ? v[j] : expm1f(v[j]);
    }
    float* outp = (LAYER == 1) ? g_h : out_arg;
    float4* po = (float4*)(outp + node * C1 + c);
    po[0] = make_float4(v[0], v[1], v[2], v[3]);
    po[1] = make_float4(v[4], v[5], v[6], v[7]);
}

// ================= launcher =================================================
extern "C" void kernel_launch(void* const* d_in, const int* in_sizes, int n_in,
                              void* d_out, int out_size) {
    const float* x     = (const float*)d_in[0];
    const int*   ei    = (const int*)  d_in[1];
    const float* W_l1  = (const float*)d_in[2];
    const float* b_l1  = (const float*)d_in[3];
    const float* W_r1  = (const float*)d_in[4];
    const float* b_r1  = (const float*)d_in[5];
    const float* att1  = (const float*)d_in[6];
    const float* bias1 = (const float*)d_in[7];
    const float* W_l2  = (const float*)d_in[8];
    const float* b_l2  = (const float*)d_in[9];
    const float* W_r2  = (const float*)d_in[10];
    const float* b_r2  = (const float*)d_in[11];
    const float* att2  = (const float*)d_in[12];
    const float* bias2 = (const float*)d_in[13];
    float* out = (float*)d_out;

    const int T = 256;
    int blkN    = (NN + T - 1) / T;
    int blkE    = (ETOT + T - 1) / T;
    int blkNode = (NN + 7) / 8;        // warp per node
    int blkG1   = (NN + 15) / 16;

    // CSR build
    zero_deg<<<blkN, T>>>();
    csr_count<<<blkE, T>>>(ei);
    csr_scan<<<1, 1024>>>();
    csr_scatter<<<blkE, T>>>(ei);

    // layer 1
    gemm1_kernel<<<blkG1, T>>>(x, W_l1, b_l1, W_r1, b_r1);
    fused_edge<1><<<blkNode, T>>>(att1, bias1, nullptr);

    // layer 2
    dim3 g2((NN + 63) / 64, 4);
    gemm_dual<<<g2, T>>>(W_l2, b_l2, W_r2, b_r2);
    fused_edge<2><<<blkNode, T>>>(att2, bias2, out);
}

// round 6
// speedup vs baseline: 3.0362x; 1.0460x over previous
#include <cuda_runtime.h>
#include <math.h>

#define NN    50000
#define EE    400000
#define ETOT  (NN + EE)
#define C1    256
#define KIN   20
#define NEG_SLOPE 0.2f
#define EPSS  1e-16f

// ---------------- scratch (static device globals; no allocations) ----------
__device__ float g_xl1[NN * C1];
__device__ float g_xr1[NN * C1];
__device__ float g_h[NN * C1];      // ELU(layer-1 output)
__device__ float g_xl2[NN * C1];
__device__ float g_xr2[NN * C1];
__device__ int   g_deg[NN];         // degree counts, then scatter cursor
__device__ int   g_off[NN + 1];     // CSR offsets
__device__ int   g_csr_src[ETOT];

__device__ __forceinline__ float lrelu(float v) {
    return v > 0.0f ? v : NEG_SLOPE * v;
}

// ---- packed f32x2 (FFMA2) helpers ----
__device__ __forceinline__ unsigned long long pack2(float lo, float hi) {
    unsigned long long r;
    asm("mov.b64 %0, {%1, %2};" : "=l"(r) : "f"(lo), "f"(hi));
    return r;
}
__device__ __forceinline__ unsigned long long fma2(unsigned long long a,
                                                   unsigned long long b,
                                                   unsigned long long c) {
    unsigned long long d;
    asm("fma.rn.f32x2 %0, %1, %2, %3;" : "=l"(d) : "l"(a), "l"(b), "l"(c));
    return d;
}
__device__ __forceinline__ float2 unpack2(unsigned long long v) {
    float lo, hi;
    asm("mov.b64 {%0, %1}, %2;" : "=f"(lo), "=f"(hi) : "l"(v));
    return make_float2(lo, hi);
}

// ================= CSR construction =================
__global__ void zero_deg() {
    int i = blockIdx.x * blockDim.x + threadIdx.x;
    if (i < NN) g_deg[i] = 0;
}

__global__ void csr_count(const int* __restrict__ ei) {
    int e = blockIdx.x * blockDim.x + threadIdx.x;
    if (e >= ETOT) return;
    int dst = (e < EE) ? ei[EE + e] : e - EE;
    atomicAdd(&g_deg[dst], 1);
}

// single-block exclusive scan over g_deg -> g_off; also zeroes g_deg (cursor)
__global__ void csr_scan() {
    int tid = threadIdx.x;
    int lane = tid & 31, wid = tid >> 5;
    __shared__ int wsum[32];
    __shared__ int carry_s;
    if (tid == 0) carry_s = 0;
    __syncthreads();
    for (int base = 0; base < NN; base += 1024) {
        __syncthreads();
        int i = base + tid;
        int v = (i < NN) ? g_deg[i] : 0;
        if (i < NN) g_deg[i] = 0;
        int x = v;
        #pragma unroll
        for (int o = 1; o < 32; o <<= 1) {
            int y = __shfl_up_sync(0xffffffffu, x, o);
            if (lane >= o) x += y;
        }
        if (lane == 31) wsum[wid] = x;
        __syncthreads();
        if (wid == 0) {
            int w = wsum[lane];
            #pragma unroll
            for (int o = 1; o < 32; o <<= 1) {
                int y = __shfl_up_sync(0xffffffffu, w, o);
                if (lane >= o) w += y;
            }
            wsum[lane] = w;
        }
        __syncthreads();
        int blockincl = x + (wid > 0 ? wsum[wid - 1] : 0);
        int excl = carry_s + blockincl - v;
        if (i < NN) g_off[i] = excl;
        __syncthreads();
        if (tid == 1023) carry_s += blockincl;
    }
    __syncthreads();
    if (tid == 0) g_off[NN] = carry_s;
}

__global__ void csr_scatter(const int* __restrict__ ei) {
    int e = blockIdx.x * blockDim.x + threadIdx.x;
    if (e >= ETOT) return;
    int src, dst;
    if (e < EE) { src = ei[e]; dst = ei[EE + e]; }
    else        { src = dst = e - EE; }
    int pos = g_off[dst] + atomicAdd(&g_deg[dst], 1);
    g_csr_src[pos] = src;
}

// ================= layer-1 GEMM: x[N,20]@W[20,256]+b (two outputs) =========
__global__ void gemm1_kernel(const float* __restrict__ x,
                             const float* __restrict__ Wl, const float* __restrict__ bl,
                             const float* __restrict__ Wr, const float* __restrict__ br) {
    __shared__ float swl[KIN * 256];
    __shared__ float swr[KIN * 256];
    __shared__ float sx[16][KIN];
    int tid = threadIdx.x;
    for (int i = tid; i < KIN * 256; i += 256) { swl[i] = Wl[i]; swr[i] = Wr[i]; }
    int nb = blockIdx.x * 16;
    for (int i = tid; i < 16 * KIN; i += 256) {
        int node = nb + i / KIN;
        sx[i / KIN][i % KIN] = (node < NN) ? x[node * KIN + (i % KIN)] : 0.0f;
    }
    __syncthreads();
    float bL = bl[tid], bR = br[tid];
    for (int i = 0; i < 16; i++) {
        int node = nb + i;
        if (node >= NN) break;
        float al = bL, ar = bR;
        #pragma unroll
        for (int k = 0; k < KIN; k++) {
            float xv = sx[i][k];
            al = fmaf(xv, swl[k * 256 + tid], al);
            ar = fmaf(xv, swr[k * 256 + tid], ar);
        }
        g_xl1[node * 256 + tid] = al;
        g_xr1[node * 256 + tid] = ar;
    }
}

// ================= dual layer-2 GEMM, 128x64 tile, 8x4x2 per thread =========
// Per k-step per thread: 32B A + 32B B for 64 FMAs (1.0 B/FMA) -> LDS and
// FFMA2 pipes balanced at the 128 FMA/cyc/SM ceiling.
__global__ void __launch_bounds__(256, 2)
gemm_dual(const float* __restrict__ Wl, const float* __restrict__ bl,
          const float* __restrict__ Wr, const float* __restrict__ br) {
    const float* __restrict__ A = g_h;
    __shared__ float As[16][128];
    __shared__ float Bl[16][64];
    __shared__ float Br[16][64];
    int tid = threadIdx.x;
    int tx = tid & 15;          // col group: 4 cols
    int ty = tid >> 4;          // row group: 8 rows
    int row0 = blockIdx.x * 128;
    int col0 = blockIdx.y * 64;

    unsigned long long accL[8][2], accR[8][2];
    #pragma unroll
    for (int i = 0; i < 8; i++) {
        accL[i][0] = 0ull; accL[i][1] = 0ull;
        accR[i][0] = 0ull; accR[i][1] = 0ull;
    }

    for (int kt = 0; kt < 256; kt += 16) {
        // A tile: 128 rows x 16 k = 2048 elems, 8 per thread
        #pragma unroll
        for (int j = 0; j < 8; j++) {
            int i = tid + j * 256;
            int m = i >> 4, k = i & 15;
            int row = row0 + m;
            As[k][m] = (row < NN) ? A[row * 256 + kt + k] : 0.0f;
        }
        // B tiles: 16 k x 64 cols = 1024 elems each, 4 per thread
        #pragma unroll
        for (int j = 0; j < 4; j++) {
            int i = tid + j * 256;
            int k = i >> 6, col = i & 63;
            Bl[k][col] = Wl[(kt + k) * 256 + col0 + col];
            Br[k][col] = Wr[(kt + k) * 256 + col0 + col];
        }
        __syncthreads();
        #pragma unroll
        for (int k = 0; k < 16; k++) {
            float4 a0 = *(const float4*)&As[k][ty * 8];
            float4 a1 = *(const float4*)&As[k][ty * 8 + 4];
            ulonglong2 b  = *(const ulonglong2*)&Bl[k][tx * 4];
            ulonglong2 b2 = *(const ulonglong2*)&Br[k][tx * 4];
            unsigned long long ap[8];
            ap[0] = pack2(a0.x, a0.x); ap[1] = pack2(a0.y, a0.y);
            ap[2] = pack2(a0.z, a0.z); ap[3] = pack2(a0.w, a0.w);
            ap[4] = pack2(a1.x, a1.x); ap[5] = pack2(a1.y, a1.y);
            ap[6] = pack2(a1.z, a1.z); ap[7] = pack2(a1.w, a1.w);
            #pragma unroll
            for (int i = 0; i < 8; i++) {
                accL[i][0] = fma2(ap[i], b.x,  accL[i][0]);
                accL[i][1] = fma2(ap[i], b.y,  accL[i][1]);
                accR[i][0] = fma2(ap[i], b2.x, accR[i][0]);
                accR[i][1] = fma2(ap[i], b2.y, accR[i][1]);
            }
        }
        __syncthreads();
    }
    #pragma unroll
    for (int i = 0; i < 8; i++) {
        int row = row0 + ty * 8 + i;
        if (row >= NN) continue;
        int col = col0 + tx * 4;
        float2 l0 = unpack2(accL[i][0]), l1 = unpack2(accL[i][1]);
        float2 r0 = unpack2(accR[i][0]), r1 = unpack2(accR[i][1]);
        float4 vl, vr;
        vl.x = l0.x + bl[col + 0]; vl.y = l0.y + bl[col + 1];
        vl.z = l1.x + bl[col + 2]; vl.w = l1.y + bl[col + 3];
        vr.x = r0.x + br[col + 0]; vr.y = r0.y + br[col + 1];
        vr.z = r1.x + br[col + 2]; vr.w = r1.y + br[col + 3];
        *(float4*)&g_xl2[row * 256 + col] = vl;
        *(float4*)&g_xr2[row * 256 + col] = vr;
    }
}

// ================= fused edge pass: logits + online softmax + aggregate =====
template<int LAYER>
__global__ void fused_edge(const float* __restrict__ att,
                           const float* __restrict__ bias,
                           float* __restrict__ out_arg) {
    const float* __restrict__ xl = (LAYER == 1) ? g_xl1 : g_xl2;
    const float* __restrict__ xr = (LAYER == 1) ? g_xr1 : g_xr2;

    int node = (blockIdx.x * blockDim.x + threadIdx.x) >> 5;
    int lane = threadIdx.x & 31;
    if (node >= NN) return;
    int s0 = g_off[node], s1 = g_off[node + 1];
    int c = lane * 8;

    const float4* pr = (const float4*)(xr + node * C1 + c);
    float4 r0 = pr[0], r1 = pr[1];
    const float4* pa = (const float4*)(att + c);
    float4 w0 = pa[0], w1 = pa[1];

    float m = -INFINITY, ssum = 0.0f;
    float4 acc0 = make_float4(0.f, 0.f, 0.f, 0.f);
    float4 acc1 = make_float4(0.f, 0.f, 0.f, 0.f);

    int src = g_csr_src[s0];
    const float4* pl = (const float4*)(xl + src * C1 + c);
    float4 l0 = pl[0], l1 = pl[1];

    for (int s = s0; s < s1; s++) {
        float4 c0 = l0, c1 = l1;
        if (s + 1 < s1) {
            int nsrc = g_csr_src[s + 1];
            const float4* pn = (const float4*)(xl + nsrc * C1 + c);
            l0 = pn[0], l1 = pn[1];
        }
        float p;
        p  =        w0.x * lrelu(c0.x + r0.x);
        p = fmaf(w0.y, lrelu(c0.y + r0.y), p);
        p = fmaf(w0.z, lrelu(c0.z + r0.z), p);
        p = fmaf(w0.w, lrelu(c0.w + r0.w), p);
        p = fmaf(w1.x, lrelu(c1.x + r1.x), p);
        p = fmaf(w1.y, lrelu(c1.y + r1.y), p);
        p = fmaf(w1.z, lrelu(c1.z + r1.z), p);
        p = fmaf(w1.w, lrelu(c1.w + r1.w), p);
        if (LAYER == 1) {
            p += __shfl_xor_sync(0xffffffffu, p, 4);
            p += __shfl_xor_sync(0xffffffffu, p, 2);
            p += __shfl_xor_sync(0xffffffffu, p, 1);
        } else {
            #pragma unroll
            for (int off = 16; off > 0; off >>= 1)
                p += __shfl_xor_sync(0xffffffffu, p, off);
        }
        if (p > m) {
            float sc = __expf(m - p);
            ssum *= sc;
            acc0.x *= sc; acc0.y *= sc; acc0.z *= sc; acc0.w *= sc;
            acc1.x *= sc; acc1.y *= sc; acc1.z *= sc; acc1.w *= sc;
            m = p;
        }
        float wgt = __expf(p - m);
        ssum += wgt;
        acc0.x = fmaf(wgt, c0.x, acc0.x); acc0.y = fmaf(wgt, c0.y, acc0.y);
        acc0.z = fmaf(wgt, c0.z, acc0.z); acc0.w = fmaf(wgt, c0.w, acc0.w);
        acc1.x = fmaf(wgt, c1.x, acc1.x); acc1.y = fmaf(wgt, c1.y, acc1.y);
        acc1.z = fmaf(wgt, c1.z, acc1.z); acc1.w = fmaf(wgt, c1.w, acc1.w);
    }

    float inv = 1.0f / (ssum + EPSS);
    const float4* pb = (const float4*)(bias + c);
    float4 b0 = pb[0], b1 = pb[1];
    float v[8] = { acc0.x * inv + b0.x, acc0.y * inv + b0.y,
                   acc0.z * inv + b0.z, acc0.w * inv + b0.w,
                   acc1.x * inv + b1.x, acc1.y * inv + b1.y,
                   acc1.z * inv + b1.z, acc1.w * inv + b1.w };
    if (LAYER == 1) {
        #pragma unroll
        for (int j = 0; j < 8; j++) v[j] = v[j] > 0.0f ? v[j] : expm1f(v[j]);
    }
    float* outp = (LAYER == 1) ? g_h : out_arg;
    float4* po = (float4*)(outp + node * C1 + c);
    po[0] = make_float4(v[0], v[1], v[2], v[3]);
    po[1] = make_float4(v[4], v[5], v[6], v[7]);
}

// ================= launcher =================================================
extern "C" void kernel_launch(void* const* d_in, const int* in_sizes, int n_in,
                              void* d_out, int out_size) {
    const float* x     = (const float*)d_in[0];
    const int*   ei    = (const int*)  d_in[1];
    const float* W_l1  = (const float*)d_in[2];
    const float* b_l1  = (const float*)d_in[3];
    const float* W_r1  = (const float*)d_in[4];
    const float* b_r1  = (const float*)d_in[5];
    const float* att1  = (const float*)d_in[6];
    const float* bias1 = (const float*)d_in[7];
    const float* W_l2  = (const float*)d_in[8];
    const float* b_l2  = (const float*)d_in[9];
    const float* W_r2  = (const float*)d_in[10];
    const float* b_r2  = (const float*)d_in[11];
    const float* att2  = (const float*)d_in[12];
    const float* bias2 = (const float*)d_in[13];
    float* out = (float*)d_out;

    const int T = 256;
    int blkN    = (NN + T - 1) / T;
    int blkE    = (ETOT + T - 1) / T;
    int blkNode = (NN + 7) / 8;        // warp per node
    int blkG1   = (NN + 15) / 16;

    // CSR build
    zero_deg<<<blkN, T>>>();
    csr_count<<<blkE, T>>>(ei);
    csr_scan<<<1, 1024>>>();
    csr_scatter<<<blkE, T>>>(ei);

    // layer 1
    gemm1_kernel<<<blkG1, T>>>(x, W_l1, b_l1, W_r1, b_r1);
    fused_edge<1><<<blkNode, T>>>(att1, bias1, nullptr);

    // layer 2
    dim3 g2((NN + 127) / 128, 4);
    gemm_dual<<<g2, T>>>(W_l2, b_l2, W_r2, b_r2);
    fused_edge<2><<<blkNode, T>>>(att2, bias2, out);
}

// round 7
// speedup vs baseline: 3.2090x; 1.0569x over previous
#include <cuda_runtime.h>
#include <math.h>

#define NN    50000
#define EE    400000
#define ETOT  (NN + EE)
#define C1    256
#define KIN   20
#define NEG_SLOPE 0.2f
#define EPSS  1e-16f

// ---------------- scratch (static device globals; no allocations) ----------
__device__ float g_xl1[NN * C1];
__device__ float g_xr1[NN * C1];
__device__ float g_h[NN * C1];      // ELU(layer-1 output)
__device__ float g_xl2[NN * C1];
__device__ float g_xr2[NN * C1];
__device__ int   g_deg[NN];         // degree counts, then scatter cursor
__device__ int   g_off[NN + 1];     // CSR offsets
__device__ int   g_csr_src[ETOT];

__device__ __forceinline__ float lrelu(float v) {
    return v > 0.0f ? v : NEG_SLOPE * v;
}

// ---- packed f32x2 (FFMA2) helpers ----
__device__ __forceinline__ unsigned long long pack2(float lo, float hi) {
    unsigned long long r;
    asm("mov.b64 %0, {%1, %2};" : "=l"(r) : "f"(lo), "f"(hi));
    return r;
}
__device__ __forceinline__ unsigned long long fma2(unsigned long long a,
                                                   unsigned long long b,
                                                   unsigned long long c) {
    unsigned long long d;
    asm("fma.rn.f32x2 %0, %1, %2, %3;" : "=l"(d) : "l"(a), "l"(b), "l"(c));
    return d;
}
__device__ __forceinline__ float2 unpack2(unsigned long long v) {
    float lo, hi;
    asm("mov.b64 {%0, %1}, %2;" : "=f"(lo), "=f"(hi) : "l"(v));
    return make_float2(lo, hi);
}

// ================= CSR construction =================
__global__ void zero_deg() {
    int i = blockIdx.x * blockDim.x + threadIdx.x;
    if (i < NN) g_deg[i] = 0;
}

__global__ void csr_count(const int* __restrict__ ei) {
    int e = blockIdx.x * blockDim.x + threadIdx.x;
    if (e >= ETOT) return;
    int dst = (e < EE) ? ei[EE + e] : e - EE;
    atomicAdd(&g_deg[dst], 1);
}

// single-block exclusive scan over g_deg -> g_off; also zeroes g_deg (cursor)
__global__ void csr_scan() {
    int tid = threadIdx.x;
    int lane = tid & 31, wid = tid >> 5;
    __shared__ int wsum[32];
    __shared__ int carry_s;
    if (tid == 0) carry_s = 0;
    __syncthreads();
    for (int base = 0; base < NN; base += 1024) {
        __syncthreads();
        int i = base + tid;
        int v = (i < NN) ? g_deg[i] : 0;
        if (i < NN) g_deg[i] = 0;
        int x = v;
        #pragma unroll
        for (int o = 1; o < 32; o <<= 1) {
            int y = __shfl_up_sync(0xffffffffu, x, o);
            if (lane >= o) x += y;
        }
        if (lane == 31) wsum[wid] = x;
        __syncthreads();
        if (wid == 0) {
            int w = wsum[lane];
            #pragma unroll
            for (int o = 1; o < 32; o <<= 1) {
                int y = __shfl_up_sync(0xffffffffu, w, o);
                if (lane >= o) w += y;
            }
            wsum[lane] = w;
        }
        __syncthreads();
        int blockincl = x + (wid > 0 ? wsum[wid - 1] : 0);
        int excl = carry_s + blockincl - v;
        if (i < NN) g_off[i] = excl;
        __syncthreads();
        if (tid == 1023) carry_s += blockincl;
    }
    __syncthreads();
    if (tid == 0) g_off[NN] = carry_s;
}

__global__ void csr_scatter(const int* __restrict__ ei) {
    int e = blockIdx.x * blockDim.x + threadIdx.x;
    if (e >= ETOT) return;
    int src, dst;
    if (e < EE) { src = ei[e]; dst = ei[EE + e]; }
    else        { src = dst = e - EE; }
    int pos = g_off[dst] + atomicAdd(&g_deg[dst], 1);
    g_csr_src[pos] = src;
}

// ================= layer-1 GEMM: x[N,20]@W[20,256]+b, 64 rows/block ========
__global__ void gemm1_kernel(const float* __restrict__ x,
                             const float* __restrict__ Wl, const float* __restrict__ bl,
                             const float* __restrict__ Wr, const float* __restrict__ br) {
    __shared__ float swl[KIN * 256];
    __shared__ float swr[KIN * 256];
    __shared__ float sx[64][KIN];
    int tid = threadIdx.x;
    for (int i = tid; i < KIN * 256; i += 256) { swl[i] = Wl[i]; swr[i] = Wr[i]; }
    int nb = blockIdx.x * 64;
    for (int i = tid; i < 64 * KIN; i += 256) {
        int node = nb + i / KIN;
        sx[i / KIN][i % KIN] = (node < NN) ? x[node * KIN + (i % KIN)] : 0.0f;
    }
    __syncthreads();
    float bL = bl[tid], bR = br[tid];
    #pragma unroll 4
    for (int i = 0; i < 64; i++) {
        int node = nb + i;
        if (node >= NN) break;
        float al = bL, ar = bR;
        #pragma unroll
        for (int k = 0; k < KIN; k++) {
            float xv = sx[i][k];
            al = fmaf(xv, swl[k * 256 + tid], al);
            ar = fmaf(xv, swr[k * 256 + tid], ar);
        }
        g_xl1[node * 256 + tid] = al;
        g_xr1[node * 256 + tid] = ar;
    }
}

// ================= dual layer-2 GEMM, 128x64 tile, 8x4x2 per thread =========
__global__ void __launch_bounds__(256, 2)
gemm_dual(const float* __restrict__ Wl, const float* __restrict__ bl,
          const float* __restrict__ Wr, const float* __restrict__ br) {
    const float* __restrict__ A = g_h;
    __shared__ float As[16][128];
    __shared__ float Bl[16][64];
    __shared__ float Br[16][64];
    int tid = threadIdx.x;
    int tx = tid & 15;
    int ty = tid >> 4;
    int row0 = blockIdx.x * 128;
    int col0 = blockIdx.y * 64;

    unsigned long long accL[8][2], accR[8][2];
    #pragma unroll
    for (int i = 0; i < 8; i++) {
        accL[i][0] = 0ull; accL[i][1] = 0ull;
        accR[i][0] = 0ull; accR[i][1] = 0ull;
    }

    for (int kt = 0; kt < 256; kt += 16) {
        #pragma unroll
        for (int j = 0; j < 8; j++) {
            int i = tid + j * 256;
            int m = i >> 4, k = i & 15;
            int row = row0 + m;
            As[k][m] = (row < NN) ? A[row * 256 + kt + k] : 0.0f;
        }
        #pragma unroll
        for (int j = 0; j < 4; j++) {
            int i = tid + j * 256;
            int k = i >> 6, col = i & 63;
            Bl[k][col] = Wl[(kt + k) * 256 + col0 + col];
            Br[k][col] = Wr[(kt + k) * 256 + col0 + col];
        }
        __syncthreads();
        #pragma unroll
        for (int k = 0; k < 16; k++) {
            float4 a0 = *(const float4*)&As[k][ty * 8];
            float4 a1 = *(const float4*)&As[k][ty * 8 + 4];
            ulonglong2 b  = *(const ulonglong2*)&Bl[k][tx * 4];
            ulonglong2 b2 = *(const ulonglong2*)&Br[k][tx * 4];
            unsigned long long ap[8];
            ap[0] = pack2(a0.x, a0.x); ap[1] = pack2(a0.y, a0.y);
            ap[2] = pack2(a0.z, a0.z); ap[3] = pack2(a0.w, a0.w);
            ap[4] = pack2(a1.x, a1.x); ap[5] = pack2(a1.y, a1.y);
            ap[6] = pack2(a1.z, a1.z); ap[7] = pack2(a1.w, a1.w);
            #pragma unroll
            for (int i = 0; i < 8; i++) {
                accL[i][0] = fma2(ap[i], b.x,  accL[i][0]);
                accL[i][1] = fma2(ap[i], b.y,  accL[i][1]);
                accR[i][0] = fma2(ap[i], b2.x, accR[i][0]);
                accR[i][1] = fma2(ap[i], b2.y, accR[i][1]);
            }
        }
        __syncthreads();
    }
    #pragma unroll
    for (int i = 0; i < 8; i++) {
        int row = row0 + ty * 8 + i;
        if (row >= NN) continue;
        int col = col0 + tx * 4;
        float2 l0 = unpack2(accL[i][0]), l1 = unpack2(accL[i][1]);
        float2 r0 = unpack2(accR[i][0]), r1 = unpack2(accR[i][1]);
        float4 vl, vr;
        vl.x = l0.x + bl[col + 0]; vl.y = l0.y + bl[col + 1];
        vl.z = l1.x + bl[col + 2]; vl.w = l1.y + bl[col + 3];
        vr.x = r0.x + br[col + 0]; vr.y = r0.y + br[col + 1];
        vr.z = r1.x + br[col + 2]; vr.w = r1.y + br[col + 3];
        *(float4*)&g_xl2[row * 256 + col] = vl;
        *(float4*)&g_xr2[row * 256 + col] = vr;
    }
}

// ================= fused edge pass: 2-edge pipelined online softmax =========
// Warp per node, lane owns 8 channels. Edges processed in pairs with two
// independent logit/shuffle chains (ILP x2) and prefetch depth 2 (MLP 4).
template<int LAYER>
__global__ void fused_edge(const float* __restrict__ att,
                           const float* __restrict__ bias,
                           float* __restrict__ out_arg) {
    const float* __restrict__ xl = (LAYER == 1) ? g_xl1 : g_xl2;
    const float* __restrict__ xr = (LAYER == 1) ? g_xr1 : g_xr2;

    int node = (blockIdx.x * blockDim.x + threadIdx.x) >> 5;
    int lane = threadIdx.x & 31;
    if (node >= NN) return;
    int s0 = g_off[node], s1 = g_off[node + 1];
    int c = lane * 8;

    const float4* pr = (const float4*)(xr + node * C1 + c);
    float4 r0 = pr[0], r1 = pr[1];
    const float4* pa = (const float4*)(att + c);
    float4 w0 = pa[0], w1 = pa[1];

    float m = -INFINITY, ssum = 0.0f;
    float4 acc0 = make_float4(0.f, 0.f, 0.f, 0.f);
    float4 acc1 = make_float4(0.f, 0.f, 0.f, 0.f);

    // prefetch edges s0 (A) and s0+1 (B)
    float4 A0, A1, B0, B1;
    {
        const float4* p = (const float4*)(xl + g_csr_src[s0] * C1 + c);
        A0 = p[0]; A1 = p[1];
    }
    if (s0 + 1 < s1) {
        const float4* p = (const float4*)(xl + g_csr_src[s0 + 1] * C1 + c);
        B0 = p[0]; B1 = p[1];
    }

    int s = s0;
    for (; s + 1 < s1; s += 2) {
        float4 c0 = A0, c1 = A1, d0 = B0, d1 = B1;
        if (s + 2 < s1) {
            const float4* p = (const float4*)(xl + g_csr_src[s + 2] * C1 + c);
            A0 = p[0]; A1 = p[1];
        }
        if (s + 3 < s1) {
            const float4* p = (const float4*)(xl + g_csr_src[s + 3] * C1 + c);
            B0 = p[0]; B1 = p[1];
        }
        // two independent logit chains
        float p1, p2;
        p1  =        w0.x * lrelu(c0.x + r0.x);
        p2  =        w0.x * lrelu(d0.x + r0.x);
        p1 = fmaf(w0.y, lrelu(c0.y + r0.y), p1);
        p2 = fmaf(w0.y, lrelu(d0.y + r0.y), p2);
        p1 = fmaf(w0.z, lrelu(c0.z + r0.z), p1);
        p2 = fmaf(w0.z, lrelu(d0.z + r0.z), p2);
        p1 = fmaf(w0.w, lrelu(c0.w + r0.w), p1);
        p2 = fmaf(w0.w, lrelu(d0.w + r0.w), p2);
        p1 = fmaf(w1.x, lrelu(c1.x + r1.x), p1);
        p2 = fmaf(w1.x, lrelu(d1.x + r1.x), p2);
        p1 = fmaf(w1.y, lrelu(c1.y + r1.y), p1);
        p2 = fmaf(w1.y, lrelu(d1.y + r1.y), p2);
        p1 = fmaf(w1.z, lrelu(c1.z + r1.z), p1);
        p2 = fmaf(w1.z, lrelu(d1.z + r1.z), p2);
        p1 = fmaf(w1.w, lrelu(c1.w + r1.w), p1);
        p2 = fmaf(w1.w, lrelu(d1.w + r1.w), p2);
        // interleaved shuffle reductions
        if (LAYER == 1) {
            p1 += __shfl_xor_sync(0xffffffffu, p1, 4);
            p2 += __shfl_xor_sync(0xffffffffu, p2, 4);
            p1 += __shfl_xor_sync(0xffffffffu, p1, 2);
            p2 += __shfl_xor_sync(0xffffffffu, p2, 2);
            p1 += __shfl_xor_sync(0xffffffffu, p1, 1);
            p2 += __shfl_xor_sync(0xffffffffu, p2, 1);
        } else {
            #pragma unroll
            for (int off = 16; off > 0; off >>= 1) {
                p1 += __shfl_xor_sync(0xffffffffu, p1, off);
                p2 += __shfl_xor_sync(0xffffffffu, p2, off);
            }
        }
        // merged online softmax update (one rescale per pair)
        float mp = fmaxf(p1, p2);
        if (mp > m) {
            float sc = __expf(m - mp);      // exp(-inf)=0 on first pair
            ssum *= sc;
            acc0.x *= sc; acc0.y *= sc; acc0.z *= sc; acc0.w *= sc;
            acc1.x *= sc; acc1.y *= sc; acc1.z *= sc; acc1.w *= sc;
            m = mp;
        }
        float wp = __expf(p1 - m);
        float wq = __expf(p2 - m);
        ssum += wp + wq;
        acc0.x = fmaf(wp, c0.x, fmaf(wq, d0.x, acc0.x));
        acc0.y = fmaf(wp, c0.y, fmaf(wq, d0.y, acc0.y));
        acc0.z = fmaf(wp, c0.z, fmaf(wq, d0.z, acc0.z));
        acc0.w = fmaf(wp, c0.w, fmaf(wq, d0.w, acc0.w));
        acc1.x = fmaf(wp, c1.x, fmaf(wq, d1.x, acc1.x));
        acc1.y = fmaf(wp, c1.y, fmaf(wq, d1.y, acc1.y));
        acc1.z = fmaf(wp, c1.z, fmaf(wq, d1.z, acc1.z));
        acc1.w = fmaf(wp, c1.w, fmaf(wq, d1.w, acc1.w));
    }
    // tail edge (odd degree)
    if (s < s1) {
        float4 c0 = A0, c1 = A1;
        float p1;
        p1  =        w0.x * lrelu(c0.x + r0.x);
        p1 = fmaf(w0.y, lrelu(c0.y + r0.y), p1);
        p1 = fmaf(w0.z, lrelu(c0.z + r0.z), p1);
        p1 = fmaf(w0.w, lrelu(c0.w + r0.w), p1);
        p1 = fmaf(w1.x, lrelu(c1.x + r1.x), p1);
        p1 = fmaf(w1.y, lrelu(c1.y + r1.y), p1);
        p1 = fmaf(w1.z, lrelu(c1.z + r1.z), p1);
        p1 = fmaf(w1.w, lrelu(c1.w + r1.w), p1);
        if (LAYER == 1) {
            p1 += __shfl_xor_sync(0xffffffffu, p1, 4);
            p1 += __shfl_xor_sync(0xffffffffu, p1, 2);
            p1 += __shfl_xor_sync(0xffffffffu, p1, 1);
        } else {
            #pragma unroll
            for (int off = 16; off > 0; off >>= 1)
                p1 += __shfl_xor_sync(0xffffffffu, p1, off);
        }
        if (p1 > m) {
            float sc = __expf(m - p1);
            ssum *= sc;
            acc0.x *= sc; acc0.y *= sc; acc0.z *= sc; acc0.w *= sc;
            acc1.x *= sc; acc1.y *= sc; acc1.z *= sc; acc1.w *= sc;
            m = p1;
        }
        float wp = __expf(p1 - m);
        ssum += wp;
        acc0.x = fmaf(wp, c0.x, acc0.x); acc0.y = fmaf(wp, c0.y, acc0.y);
        acc0.z = fmaf(wp, c0.z, acc0.z); acc0.w = fmaf(wp, c0.w, acc0.w);
        acc1.x = fmaf(wp, c1.x, acc1.x); acc1.y = fmaf(wp, c1.y, acc1.y);
        acc1.z = fmaf(wp, c1.z, acc1.z); acc1.w = fmaf(wp, c1.w, acc1.w);
    }

    float inv = 1.0f / (ssum + EPSS);
    const float4* pb = (const float4*)(bias + c);
    float4 b0 = pb[0], b1 = pb[1];
    float v[8] = { acc0.x * inv + b0.x, acc0.y * inv + b0.y,
                   acc0.z * inv + b0.z, acc0.w * inv + b0.w,
                   acc1.x * inv + b1.x, acc1.y * inv + b1.y,
                   acc1.z * inv + b1.z, acc1.w * inv + b1.w };
    if (LAYER == 1) {
        #pragma unroll
        for (int j = 0; j < 8; j++) v[j] = v[j] > 0.0f ? v[j] : expm1f(v[j]);
    }
    float* outp = (LAYER == 1) ? g_h : out_arg;
    float4* po = (float4*)(outp + node * C1 + c);
    po[0] = make_float4(v[0], v[1], v[2], v[3]);
    po[1] = make_float4(v[4], v[5], v[6], v[7]);
}

// ================= launcher =================================================
extern "C" void kernel_launch(void* const* d_in, const int* in_sizes, int n_in,
                              void* d_out, int out_size) {
    const float* x     = (const float*)d_in[0];
    const int*   ei    = (const int*)  d_in[1];
    const float* W_l1  = (const float*)d_in[2];
    const float* b_l1  = (const float*)d_in[3];
    const float* W_r1  = (const float*)d_in[4];
    const float* b_r1  = (const float*)d_in[5];
    const float* att1  = (const float*)d_in[6];
    const float* bias1 = (const float*)d_in[7];
    const float* W_l2  = (const float*)d_in[8];
    const float* b_l2  = (const float*)d_in[9];
    const float* W_r2  = (const float*)d_in[10];
    const float* b_r2  = (const float*)d_in[11];
    const float* att2  = (const float*)d_in[12];
    const float* bias2 = (const float*)d_in[13];
    float* out = (float*)d_out;

    const int T = 256;
    int blkN    = (NN + T - 1) / T;
    int blkE    = (ETOT + T - 1) / T;
    int blkNode = (NN + 7) / 8;        // warp per node
    int blkG1   = (NN + 63) / 64;

    // CSR build
    zero_deg<<<blkN, T>>>();
    csr_count<<<blkE, T>>>(ei);
    csr_scan<<<1, 1024>>>();
    csr_scatter<<<blkE, T>>>(ei);

    // layer 1
    gemm1_kernel<<<blkG1, T>>>(x, W_l1, b_l1, W_r1, b_r1);
    fused_edge<1><<<blkNode, T>>>(att1, bias1, nullptr);

    // layer 2
    dim3 g2((NN + 127) / 128, 4);
    gemm_dual<<<g2, T>>>(W_l2, b_l2, W_r2, b_r2);
    fused_edge<2><<<blkNode, T>>>(att2, bias2, out);
}